// round 3
// baseline (speedup 1.0000x reference)
#include <cuda_runtime.h>
#include <math.h>

// Problem constants
#define Bb   8
#define Ss   256
#define Nn   512
#define Ii   32
#define HH   64
#define Oo   32
#define BS   (Bb*Ss)                 // 2048
#define RTOT (BS*Nn)                 // 1,048,576 rows
#define BN   (Bb*Nn)                 // 4096 GRU sequences

typedef unsigned long long ull;

// Scratch (device globals; allocation-free kernel_launch)
__device__ float g_sp  [(size_t)RTOT * Oo];   // 134 MB: GCN2 output (pre-adj)
__device__ float g_tanh[(size_t)RTOT * Oo];   // 134 MB: tanh(adj @ sp)
__device__ float g_gi  [(size_t)RTOT * 96];   // 402 MB: GRU input gates

__device__ __forceinline__ ull pack2(float lo, float hi) {
    ull r; asm("mov.b64 %0,{%1,%2};" : "=l"(r) : "f"(lo), "f"(hi)); return r;
}
__device__ __forceinline__ float2 unpack2(ull v) {
    float2 f; asm("mov.b64 {%0,%1},%2;" : "=f"(f.x), "=f"(f.y) : "l"(v)); return f;
}
__device__ __forceinline__ ull fma2(ull a, ull b, ull c) {
    ull d; asm("fma.rn.f32x2 %0,%1,%2,%3;" : "=l"(d) : "l"(a), "l"(b), "l"(c)); return d;
}

__device__ __forceinline__ float warp_sum(float v) {
    #pragma unroll
    for (int o = 16; o > 0; o >>= 1) v += __shfl_xor_sync(0xffffffffu, v, o);
    return v;
}
__device__ __forceinline__ float sigmoid_f(float x) {
    return __fdividef(1.f, 1.f + __expf(-x));
}
__device__ __forceinline__ float tanh_f(float x) {
    float ax = fabsf(x);
    float e  = __expf(-2.f * ax);
    float t  = (1.f - e) * __fdividef(1.f, 1.f + e);
    return copysignf(t, x);
}

// ---------------------------------------------------------------------------
// K1: per row: t = x@W1+b1 ; h = relu(LN64(t)) ; sp = h@W2+b2+x
// Warp handles 4 rows. Broadcast vectors (x, h) staged in per-warp smem and
// consumed as LDS.64 pairs feeding packed f32x2 FMAs. No shuffles in GEMVs.
// ---------------------------------------------------------------------------
__global__ __launch_bounds__(256) void k1_gcn(
    const float* __restrict__ x,  const float* __restrict__ W1,
    const float* __restrict__ b1, const float* __restrict__ g1,
    const float* __restrict__ be1,const float* __restrict__ W2,
    const float* __restrict__ b2, float* __restrict__ sp_out)
{
    __shared__ ull W1p[16][64];   // (W1[2jp][j], W1[2jp+1][j])
    __shared__ ull W2p[32][32];   // (W2[2kp][o], W2[2kp+1][o])
    __shared__ float b1s[64], g1s[64], be1s[64], b2s[32];
    __shared__ float xs[8][4][32];
    __shared__ float hs[8][4][64];

    int tid = threadIdx.x;
    for (int i = tid; i < 1024; i += 256) {
        int jp = i >> 6, j = i & 63;
        W1p[jp][j] = pack2(W1[(2*jp)*64 + j], W1[(2*jp+1)*64 + j]);
    }
    for (int i = tid; i < 1024; i += 256) {
        int kp = i >> 5, o = i & 31;
        W2p[kp][o] = pack2(W2[(2*kp)*32 + o], W2[(2*kp+1)*32 + o]);
    }
    if (tid < 64) { b1s[tid] = b1[tid]; g1s[tid] = g1[tid]; be1s[tid] = be1[tid]; }
    if (tid < 32) b2s[tid] = b2[tid];
    __syncthreads();

    int lane = tid & 31, wr = tid >> 5;
    size_t r0 = ((size_t)blockIdx.x * 8 + wr) * 4;

    float xv[4];
    #pragma unroll
    for (int q = 0; q < 4; q++) {
        xv[q] = x[(r0 + q) * 32 + lane];
        xs[wr][q][lane] = xv[q];
    }
    __syncwarp();

    ull t0p[4], t1p[4];
    #pragma unroll
    for (int q = 0; q < 4; q++) {
        t0p[q] = pack2(b1s[lane], 0.f);
        t1p[q] = pack2(b1s[lane + 32], 0.f);
    }
    #pragma unroll
    for (int jp = 0; jp < 16; jp++) {
        ull w0 = W1p[jp][lane], w1 = W1p[jp][lane + 32];
        #pragma unroll
        for (int q = 0; q < 4; q++) {
            ull xp = *(const ull*)&xs[wr][q][2 * jp];
            t0p[q] = fma2(xp, w0, t0p[q]);
            t1p[q] = fma2(xp, w1, t1p[q]);
        }
    }

    #pragma unroll
    for (int q = 0; q < 4; q++) {
        float2 a = unpack2(t0p[q]); float t0 = a.x + a.y;
        float2 b = unpack2(t1p[q]); float t1 = b.x + b.y;
        float mu = warp_sum(t0 + t1) * (1.f / 64.f);
        float d0 = t0 - mu, d1 = t1 - mu;
        float var = warp_sum(d0 * d0 + d1 * d1) * (1.f / 64.f);
        float rstd = rsqrtf(var + 1e-5f);
        float h0 = fmaxf(fmaf(d0 * rstd, g1s[lane],      be1s[lane]),      0.f);
        float h1 = fmaxf(fmaf(d1 * rstd, g1s[lane + 32], be1s[lane + 32]), 0.f);
        hs[wr][q][lane]      = h0;
        hs[wr][q][lane + 32] = h1;
    }
    __syncwarp();

    ull spp[4];
    #pragma unroll
    for (int q = 0; q < 4; q++) spp[q] = pack2(b2s[lane] + xv[q], 0.f);
    #pragma unroll
    for (int kp = 0; kp < 32; kp++) {
        ull wv = W2p[kp][lane];
        #pragma unroll
        for (int q = 0; q < 4; q++) {
            ull hp = *(const ull*)&hs[wr][q][2 * kp];
            spp[q] = fma2(hp, wv, spp[q]);
        }
    }
    #pragma unroll
    for (int q = 0; q < 4; q++) {
        float2 s = unpack2(spp[q]);
        sp_out[(r0 + q) * 32 + lane] = s.x + s.y;
    }
}

// ---------------------------------------------------------------------------
// K2: out[bs,n,f] = tanh( sum_m adj[n,m] * sp[bs,m,f] )
// 256 threads, C-tile 256n x 32f, thread computes 8n (as 4 n-pairs) x 4f with
// packed f32x2 FMAs. adj staged transposed (n-pairs contiguous), sp staged as
// duplicated (b,b) pairs.
// ---------------------------------------------------------------------------
__global__ __launch_bounds__(256) void k2_adj(
    const float* __restrict__ adj, const float* __restrict__ sp,
    float* __restrict__ out)
{
    __shared__ float adjT[32][256];   // [mm][nn]  32 KB
    __shared__ ull   sd[32][33];      // [f][m] duplicated pairs, padded

    int bs  = blockIdx.y;
    int n0  = blockIdx.x * 256;
    int tid = threadIdx.x;
    int fj  = (tid & 7) * 4;
    int ng  = tid >> 3;
    const float* spb = sp + (size_t)bs * (Nn * Oo);

    ull acc[4][4];
    #pragma unroll
    for (int p = 0; p < 4; p++)
        #pragma unroll
        for (int j = 0; j < 4; j++) acc[p][j] = 0ULL;

    for (int mc = 0; mc < 512; mc += 32) {
        __syncthreads();
        {
            const float* arow = adj + (size_t)(n0 + tid) * 512 + mc;
            #pragma unroll
            for (int u = 0; u < 8; u++) {
                float4 v = *(const float4*)(arow + u * 4);
                adjT[u*4+0][tid] = v.x; adjT[u*4+1][tid] = v.y;
                adjT[u*4+2][tid] = v.z; adjT[u*4+3][tid] = v.w;
            }
            int m = tid >> 3;
            float4 v = *(const float4*)&spb[(size_t)(mc + m) * 32 + fj];
            sd[fj+0][m] = pack2(v.x, v.x); sd[fj+1][m] = pack2(v.y, v.y);
            sd[fj+2][m] = pack2(v.z, v.z); sd[fj+3][m] = pack2(v.w, v.w);
        }
        __syncthreads();

        #pragma unroll
        for (int mm = 0; mm < 32; mm++) {
            ull b0 = sd[fj+0][mm], b1 = sd[fj+1][mm];
            ull b2 = sd[fj+2][mm], b3 = sd[fj+3][mm];
            const ull* ar = (const ull*)&adjT[mm][ng * 8];
            ull a0 = ar[0], a1 = ar[1], a2 = ar[2], a3 = ar[3];
            acc[0][0]=fma2(a0,b0,acc[0][0]); acc[0][1]=fma2(a0,b1,acc[0][1]);
            acc[0][2]=fma2(a0,b2,acc[0][2]); acc[0][3]=fma2(a0,b3,acc[0][3]);
            acc[1][0]=fma2(a1,b0,acc[1][0]); acc[1][1]=fma2(a1,b1,acc[1][1]);
            acc[1][2]=fma2(a1,b2,acc[1][2]); acc[1][3]=fma2(a1,b3,acc[1][3]);
            acc[2][0]=fma2(a2,b0,acc[2][0]); acc[2][1]=fma2(a2,b1,acc[2][1]);
            acc[2][2]=fma2(a2,b2,acc[2][2]); acc[2][3]=fma2(a2,b3,acc[2][3]);
            acc[3][0]=fma2(a3,b0,acc[3][0]); acc[3][1]=fma2(a3,b1,acc[3][1]);
            acc[3][2]=fma2(a3,b2,acc[3][2]); acc[3][3]=fma2(a3,b3,acc[3][3]);
        }
    }

    #pragma unroll
    for (int p = 0; p < 4; p++) {
        float2 c0 = unpack2(acc[p][0]), c1 = unpack2(acc[p][1]);
        float2 c2 = unpack2(acc[p][2]), c3 = unpack2(acc[p][3]);
        size_t rowe = ((size_t)bs * 512 + n0 + ng * 8 + 2 * p) * 32 + fj;
        float4 lo = { tanh_f(c0.x), tanh_f(c1.x), tanh_f(c2.x), tanh_f(c3.x) };
        float4 hi = { tanh_f(c0.y), tanh_f(c1.y), tanh_f(c2.y), tanh_f(c3.y) };
        *(float4*)&out[rowe]      = lo;
        *(float4*)&out[rowe + 32] = hi;
    }
}

// ---------------------------------------------------------------------------
// K3: LN over O=32 per row, then gi = ln @ w_ih^T + b_ih (GRU order output).
// ln staged in smem; w_ih rows are jj-contiguous so pairs load natively;
// all three gate chains are f32x2 pair accumulations.
// ---------------------------------------------------------------------------
__global__ __launch_bounds__(256) void k3_ln_gi(
    const float* __restrict__ tin, const float* __restrict__ g2,
    const float* __restrict__ be2, const float* __restrict__ w_ih,
    const float* __restrict__ b_ih, float* __restrict__ gi)
{
    __shared__ ull wp[16][96];      // (w_ih[o][2jp], w_ih[o][2jp+1])
    __shared__ float lns[8][4][32];

    int tid = threadIdx.x;
    for (int i = tid; i < 1536; i += 256) {
        int jp = i / 96, o = i % 96;
        wp[jp][o] = pack2(w_ih[o * 32 + 2*jp], w_ih[o * 32 + 2*jp + 1]);
    }
    __syncthreads();

    int lane = tid & 31, wr = tid >> 5;
    size_t r0 = ((size_t)blockIdx.x * 8 + wr) * 4;
    float g2v = g2[lane], be2v = be2[lane];
    float bi0 = b_ih[lane], bi1 = b_ih[lane + 32], bi2 = b_ih[lane + 64];

    #pragma unroll
    for (int q = 0; q < 4; q++) {
        float v = tin[(r0 + q) * 32 + lane];
        float mu = warp_sum(v) * (1.f / 32.f);
        float d = v - mu;
        float var = warp_sum(d * d) * (1.f / 32.f);
        lns[wr][q][lane] = fmaf(d * rsqrtf(var + 1e-5f), g2v, be2v);
    }
    __syncwarp();

    ull a0p[4] = {0,0,0,0}, a1p[4] = {0,0,0,0}, a2p[4] = {0,0,0,0};
    #pragma unroll
    for (int jp = 0; jp < 16; jp++) {
        ull w0 = wp[jp][lane], w1 = wp[jp][lane + 32], w2 = wp[jp][lane + 64];
        #pragma unroll
        for (int q = 0; q < 4; q++) {
            ull lp = *(const ull*)&lns[wr][q][2 * jp];
            a0p[q] = fma2(lp, w0, a0p[q]);
            a1p[q] = fma2(lp, w1, a1p[q]);
            a2p[q] = fma2(lp, w2, a2p[q]);
        }
    }
    #pragma unroll
    for (int q = 0; q < 4; q++) {
        size_t r = r0 + q;
        int b = (int)(r >> 17);
        int s = (int)((r >> 9) & 255);
        int n = (int)(r & 511);
        size_t base = ((size_t)(b * 512 + n) * 256 + s) * 96;
        float2 u0 = unpack2(a0p[q]), u1 = unpack2(a1p[q]), u2 = unpack2(a2p[q]);
        gi[base + lane]      = u0.x + u0.y + bi0;
        gi[base + lane + 32] = u1.x + u1.y + bi1;
        gi[base + lane + 64] = u2.x + u2.y + bi2;
    }
}

// ---------------------------------------------------------------------------
// K4: GRU scan. One warp per (b,n); h broadcast via per-warp smem row read as
// pairs; all three gate GEMV chains are f32x2 pair sums; gi double-buffered.
// ---------------------------------------------------------------------------
__global__ __launch_bounds__(256) void k4_gru(
    const float* __restrict__ gi, const float* __restrict__ w_hh,
    const float* __restrict__ b_hh, float* __restrict__ out)
{
    __shared__ float hsm[8][32];

    int tid = threadIdx.x, lane = tid & 31, wr = tid >> 5;
    int bn = blockIdx.x * 8 + wr;
    int b = bn >> 9, n = bn & 511;

    const ull* wr0 = (const ull*)(w_hh + (size_t)lane * 32);
    const ull* wr1 = (const ull*)(w_hh + (size_t)(lane + 32) * 32);
    const ull* wr2 = (const ull*)(w_hh + (size_t)(lane + 64) * 32);
    ull w0p[16], w1p[16], w2p[16];
    #pragma unroll
    for (int m = 0; m < 16; m++) { w0p[m] = wr0[m]; w1p[m] = wr1[m]; w2p[m] = wr2[m]; }
    float bh0 = b_hh[lane], bh1 = b_hh[lane + 32], bh2 = b_hh[lane + 64];

    float h = 0.f;
    const float* gp = gi + (size_t)bn * 256 * 96;
    float q0 = gp[lane], q1 = gp[lane + 32], q2 = gp[lane + 64];

    for (int t = 0; t < 256; t++) {
        // prefetch next step's input gates
        const float* gn = gp + (size_t)((t < 255) ? (t + 1) : t) * 96;
        float p0 = gn[lane], p1 = gn[lane + 32], p2 = gn[lane + 64];

        hsm[wr][lane] = h;
        __syncwarp();
        ull a0p = 0, a1p = 0, a2p = 0;
        #pragma unroll
        for (int m = 0; m < 16; m++) {
            ull hp = *(const ull*)&hsm[wr][2 * m];
            a0p = fma2(hp, w0p[m], a0p);
            a1p = fma2(hp, w1p[m], a1p);
            a2p = fma2(hp, w2p[m], a2p);
        }
        __syncwarp();
        float2 u0 = unpack2(a0p), u1 = unpack2(a1p), u2 = unpack2(a2p);
        float gh0 = u0.x + u0.y + bh0;
        float gh1 = u1.x + u1.y + bh1;
        float gh2 = u2.x + u2.y + bh2;

        float rg = sigmoid_f(q0 + gh0);
        float zg = sigmoid_f(q1 + gh1);
        float ng = tanh_f(fmaf(rg, gh2, q2));
        h = fmaf(zg, h - ng, ng);   // (1-z)*n + z*h
        out[((size_t)(b * 256 + t) * 512 + n) * 32 + lane] = h;

        q0 = p0; q1 = p1; q2 = p2;
    }
}

// ---------------------------------------------------------------------------
extern "C" void kernel_launch(void* const* d_in, const int* in_sizes, int n_in,
                              void* d_out, int out_size)
{
    (void)in_sizes; (void)n_in; (void)out_size;
    const float* x    = (const float*)d_in[0];
    const float* adj  = (const float*)d_in[1];
    const float* W1   = (const float*)d_in[2];
    const float* b1   = (const float*)d_in[3];
    const float* g1   = (const float*)d_in[4];
    const float* be1  = (const float*)d_in[5];
    const float* W2   = (const float*)d_in[6];
    const float* b2   = (const float*)d_in[7];
    const float* g2   = (const float*)d_in[8];
    const float* be2  = (const float*)d_in[9];
    const float* w_ih = (const float*)d_in[10];
    const float* w_hh = (const float*)d_in[11];
    const float* b_ih = (const float*)d_in[12];
    const float* b_hh = (const float*)d_in[13];
    float* out = (float*)d_out;

    float *sp, *th, *gv;
    cudaGetSymbolAddress((void**)&sp, g_sp);
    cudaGetSymbolAddress((void**)&th, g_tanh);
    cudaGetSymbolAddress((void**)&gv, g_gi);

    k1_gcn<<<RTOT / 32, 256>>>(x, W1, b1, g1, be1, W2, b2, sp);
    k2_adj<<<dim3(2, BS), 256>>>(adj, sp, th);
    k3_ln_gi<<<RTOT / 32, 256>>>(th, g2, be2, w_ih, b_ih, gv);
    k4_gru<<<BN / 8, 256>>>(gv, w_hh, b_hh, out);
}

// round 4
// speedup vs baseline: 1.3090x; 1.3090x over previous
#include <cuda_runtime.h>
#include <math.h>
#include <stdint.h>

// Problem constants
#define Bb   8
#define Ss   256
#define Nn   512
#define Ii   32
#define HH   64
#define Oo   32
#define BS   (Bb*Ss)                 // 2048
#define RTOT (BS*Nn)                 // 1,048,576 rows
#define BN   (Bb*Nn)                 // 4096 GRU sequences

// Scratch (device globals; allocation-free kernel_launch)
__device__ float g_sp  [(size_t)RTOT * Oo];   // 134 MB: GCN2 output (pre-adj)
__device__ float g_tanh[(size_t)RTOT * Oo];   // 134 MB: tanh(adj @ sp)
__device__ float g_gi  [(size_t)RTOT * 96];   // 402 MB: GRU input gates
__device__ float g_adj_hi[Nn * Nn];           // 1 MB: tf32-rounded adj
__device__ float g_adj_lo[Nn * Nn];           // 1 MB: residual

__device__ __forceinline__ float warp_sum(float v) {
    #pragma unroll
    for (int o = 16; o > 0; o >>= 1) v += __shfl_xor_sync(0xffffffffu, v, o);
    return v;
}
__device__ __forceinline__ float sigmoid_f(float x) {
    return __fdividef(1.f, 1.f + __expf(-x));
}
__device__ __forceinline__ float tanh_f(float x) {
    float ax = fabsf(x);
    float e  = __expf(-2.f * ax);
    float t  = (1.f - e) * __fdividef(1.f, 1.f + e);
    return copysignf(t, x);
}
__device__ __forceinline__ float tf32_rna(float v) {
    uint32_t u; asm("cvt.rna.tf32.f32 %0,%1;" : "=r"(u) : "f"(v));
    return __uint_as_float(u);
}
__device__ __forceinline__ uint32_t as_u(float f) { return __float_as_uint(f); }

struct F4 { float x, y, z, w; };
__device__ __forceinline__ void mma_tf32(F4& d,
    uint32_t a0, uint32_t a1, uint32_t a2, uint32_t a3,
    uint32_t b0, uint32_t b1)
{
    asm volatile(
        "mma.sync.aligned.m16n8k8.row.col.f32.tf32.tf32.f32 "
        "{%0,%1,%2,%3},{%4,%5,%6,%7},{%8,%9},{%0,%1,%2,%3};"
        : "+f"(d.x), "+f"(d.y), "+f"(d.z), "+f"(d.w)
        : "r"(a0), "r"(a1), "r"(a2), "r"(a3), "r"(b0), "r"(b1));
}

// ---------------------------------------------------------------------------
// K0: split adj into tf32 hi + fp32 residual (runs once per launch; tiny)
// ---------------------------------------------------------------------------
__global__ __launch_bounds__(256) void k0_split(
    const float* __restrict__ adj, float* __restrict__ hi, float* __restrict__ lo)
{
    int i = blockIdx.x * 256 + threadIdx.x;
    float v = adj[i];
    float h = tf32_rna(v);
    hi[i] = h;
    lo[i] = v - h;
}

// ---------------------------------------------------------------------------
// K1 (R1 version): t = x@W1+b1 ; h = relu(LN64(t)) ; sp = h@W2+b2+x
// ---------------------------------------------------------------------------
__global__ __launch_bounds__(256) void k1_gcn(
    const float* __restrict__ x,  const float* __restrict__ W1,
    const float* __restrict__ b1, const float* __restrict__ g1,
    const float* __restrict__ be1,const float* __restrict__ W2,
    const float* __restrict__ b2, float* __restrict__ sp_out)
{
    __shared__ __align__(16) float W1p[2048];  // [jj][j][p]: (W1[jj][j], W1[jj][j+32])
    __shared__ __align__(16) float W2p[2048];  // [kk][j][p]: (W2[kk][j], W2[kk+32][j])
    __shared__ float b1s[64], g1s[64], be1s[64], b2s[32];

    int tid = threadIdx.x;
    for (int i = tid; i < 2048; i += 256) {
        int jj = i >> 6, rem = i & 63, j = rem >> 1, p = rem & 1;
        W1p[i] = W1[jj * 64 + j + p * 32];
        W2p[i] = W2[(jj + p * 32) * 32 + j];
    }
    if (tid < 64) { b1s[tid] = b1[tid]; g1s[tid] = g1[tid]; be1s[tid] = be1[tid]; }
    if (tid < 32) b2s[tid] = b2[tid];
    __syncthreads();

    int lane = tid & 31;
    size_t r0 = ((size_t)blockIdx.x * 8 + (tid >> 5)) * 4;

    float xv[4], t0[4], t1[4];
    #pragma unroll
    for (int q = 0; q < 4; q++) {
        xv[q] = x[(r0 + q) * 32 + lane];
        t0[q] = b1s[lane]; t1[q] = b1s[lane + 32];
    }
    #pragma unroll
    for (int jj = 0; jj < 32; jj++) {
        float2 w = *(const float2*)&W1p[jj * 64 + lane * 2];
        #pragma unroll
        for (int q = 0; q < 4; q++) {
            float xb = __shfl_sync(0xffffffffu, xv[q], jj);
            t0[q] = fmaf(xb, w.x, t0[q]);
            t1[q] = fmaf(xb, w.y, t1[q]);
        }
    }
    float h0[4], h1[4];
    #pragma unroll
    for (int q = 0; q < 4; q++) {
        float mu = warp_sum(t0[q] + t1[q]) * (1.f / 64.f);
        float d0 = t0[q] - mu, d1 = t1[q] - mu;
        float var = warp_sum(d0 * d0 + d1 * d1) * (1.f / 64.f);
        float rstd = rsqrtf(var + 1e-5f);
        h0[q] = fmaxf(fmaf(d0 * rstd, g1s[lane],      be1s[lane]),      0.f);
        h1[q] = fmaxf(fmaf(d1 * rstd, g1s[lane + 32], be1s[lane + 32]), 0.f);
    }
    float sp[4];
    #pragma unroll
    for (int q = 0; q < 4; q++) sp[q] = b2s[lane] + xv[q];
    #pragma unroll
    for (int kk = 0; kk < 32; kk++) {
        float2 w = *(const float2*)&W2p[kk * 64 + lane * 2];
        #pragma unroll
        for (int q = 0; q < 4; q++) {
            float a = __shfl_sync(0xffffffffu, h0[q], kk);
            float b = __shfl_sync(0xffffffffu, h1[q], kk);
            sp[q] = fmaf(a, w.x, fmaf(b, w.y, sp[q]));
        }
    }
    #pragma unroll
    for (int q = 0; q < 4; q++) sp_out[(r0 + q) * 32 + lane] = sp[q];
}

// ---------------------------------------------------------------------------
// K2: tf32 tensor-core GEMM with 3-term compensation.
// out[bs,n,f] = tanh( sum_m adj[n,m] * sp[bs,m,f] )
// Block: 256 thr, tile 128n x 32f x 4bs, K-chunk 32.
// adj smem tile shared by the 4 bs slices (4x adj traffic reduction).
// ---------------------------------------------------------------------------
#define K2_SMEM_FLOATS (2*128*36 + 2*4*32*36)   // 18432 floats = 73728 B

__global__ __launch_bounds__(256) void k2_mma(
    const float* __restrict__ adj_hi, const float* __restrict__ adj_lo,
    const float* __restrict__ sp, float* __restrict__ out)
{
    extern __shared__ float smem[];
    float* Ah = smem;                    // [128][36]  n-major, k padded
    float* Al = Ah + 128 * 36;
    float* Bh = Al + 128 * 36;           // [4][32][36] k-major, f padded
    float* Bl = Bh + 4 * 32 * 36;

    int tid  = threadIdx.x, lane = tid & 31, wid = tid >> 5;
    int n0   = blockIdx.x * 128;
    int bs0  = blockIdx.y * 4;
    int mbase = wid * 16;
    int r = lane >> 2, c = lane & 3;

    F4 acc[4][4];
    #pragma unroll
    for (int u = 0; u < 4; u++)
        #pragma unroll
        for (int j = 0; j < 4; j++) { acc[u][j].x = acc[u][j].y = acc[u][j].z = acc[u][j].w = 0.f; }

    for (int mc = 0; mc < 512; mc += 32) {
        __syncthreads();
        // stage adj hi/lo tiles: 128 rows x 32 k
        #pragma unroll
        for (int i = 0; i < 4; i++) {
            int q = i * 256 + tid;            // 0..1023 quads
            int n = q >> 3, k4 = (q & 7) * 4;
            size_t g = (size_t)(n0 + n) * 512 + mc + k4;
            *(float4*)&Ah[n * 36 + k4] = *(const float4*)&adj_hi[g];
            *(float4*)&Al[n * 36 + k4] = *(const float4*)&adj_lo[g];
        }
        // stage sp tiles for 4 batches, tf32-split on the fly
        {
            int k = tid >> 3, f4 = (tid & 7) * 4;
            #pragma unroll
            for (int u = 0; u < 4; u++) {
                float4 v = *(const float4*)&sp[((size_t)(bs0 + u) * 512 + mc + k) * 32 + f4];
                float hx = tf32_rna(v.x), hy = tf32_rna(v.y);
                float hz = tf32_rna(v.z), hw = tf32_rna(v.w);
                float4 hv = { hx, hy, hz, hw };
                float4 lv = { v.x - hx, v.y - hy, v.z - hz, v.w - hw };
                *(float4*)&Bh[(u * 32 + k) * 36 + f4] = hv;
                *(float4*)&Bl[(u * 32 + k) * 36 + f4] = lv;
            }
        }
        __syncthreads();

        #pragma unroll
        for (int kt = 0; kt < 4; kt++) {
            int kb = kt * 8;
            uint32_t ah0 = as_u(Ah[(mbase + r)     * 36 + kb + c]);
            uint32_t ah1 = as_u(Ah[(mbase + 8 + r) * 36 + kb + c]);
            uint32_t ah2 = as_u(Ah[(mbase + r)     * 36 + kb + 4 + c]);
            uint32_t ah3 = as_u(Ah[(mbase + 8 + r) * 36 + kb + 4 + c]);
            uint32_t al0 = as_u(Al[(mbase + r)     * 36 + kb + c]);
            uint32_t al1 = as_u(Al[(mbase + 8 + r) * 36 + kb + c]);
            uint32_t al2 = as_u(Al[(mbase + r)     * 36 + kb + 4 + c]);
            uint32_t al3 = as_u(Al[(mbase + 8 + r) * 36 + kb + 4 + c]);
            #pragma unroll
            for (int u = 0; u < 4; u++) {
                #pragma unroll
                for (int j = 0; j < 4; j++) {
                    uint32_t bh0 = as_u(Bh[(u * 32 + kb + c)     * 36 + j * 8 + r]);
                    uint32_t bh1 = as_u(Bh[(u * 32 + kb + 4 + c) * 36 + j * 8 + r]);
                    uint32_t bl0 = as_u(Bl[(u * 32 + kb + c)     * 36 + j * 8 + r]);
                    uint32_t bl1 = as_u(Bl[(u * 32 + kb + 4 + c) * 36 + j * 8 + r]);
                    mma_tf32(acc[u][j], ah0, ah1, ah2, ah3, bh0, bh1);
                    mma_tf32(acc[u][j], al0, al1, al2, al3, bh0, bh1);
                    mma_tf32(acc[u][j], ah0, ah1, ah2, ah3, bl0, bl1);
                }
            }
        }
    }

    // epilogue: tanh + store
    int c2 = (lane & 3) * 2;
    #pragma unroll
    for (int u = 0; u < 4; u++) {
        size_t bsrow = (size_t)(bs0 + u) * 512;
        #pragma unroll
        for (int j = 0; j < 4; j++) {
            int col  = j * 8 + c2;
            int row0 = n0 + mbase + r;
            float2 v0 = { tanh_f(acc[u][j].x), tanh_f(acc[u][j].y) };
            float2 v1 = { tanh_f(acc[u][j].z), tanh_f(acc[u][j].w) };
            *(float2*)&out[(bsrow + row0)     * 32 + col] = v0;
            *(float2*)&out[(bsrow + row0 + 8) * 32 + col] = v1;
        }
    }
}

// ---------------------------------------------------------------------------
// K3 (R1 version): LN over O=32 per row, then gi = ln @ w_ih^T + b_ih.
// ---------------------------------------------------------------------------
__global__ __launch_bounds__(256) void k3_ln_gi(
    const float* __restrict__ tin, const float* __restrict__ g2,
    const float* __restrict__ be2, const float* __restrict__ w_ih,
    const float* __restrict__ b_ih, float* __restrict__ gi)
{
    __shared__ __align__(16) float wT[32 * 128]; // [jj][j][p], p<3 = w_ih[(j+p*32)*32+jj]
    int tid = threadIdx.x;
    for (int i = tid; i < 4096; i += 256) {
        int jj = i >> 7, rem = i & 127, j = rem >> 2, p = rem & 3;
        wT[i] = (p < 3) ? w_ih[(j + p * 32) * 32 + jj] : 0.f;
    }
    __syncthreads();

    int lane = tid & 31;
    size_t r0 = ((size_t)blockIdx.x * 8 + (tid >> 5)) * 4;
    float g2v = g2[lane], be2v = be2[lane];
    float bi0 = b_ih[lane], bi1 = b_ih[lane + 32], bi2 = b_ih[lane + 64];

    float ln[4], acc0[4], acc1[4], acc2[4];
    #pragma unroll
    for (int q = 0; q < 4; q++) {
        float v = tin[(r0 + q) * 32 + lane];
        float mu = warp_sum(v) * (1.f / 32.f);
        float d = v - mu;
        float var = warp_sum(d * d) * (1.f / 32.f);
        ln[q] = fmaf(d * rsqrtf(var + 1e-5f), g2v, be2v);
        acc0[q] = bi0; acc1[q] = bi1; acc2[q] = bi2;
    }
    #pragma unroll
    for (int jj = 0; jj < 32; jj++) {
        float4 w = *(const float4*)&wT[jj * 128 + lane * 4];
        #pragma unroll
        for (int q = 0; q < 4; q++) {
            float lv = __shfl_sync(0xffffffffu, ln[q], jj);
            acc0[q] = fmaf(lv, w.x, acc0[q]);
            acc1[q] = fmaf(lv, w.y, acc1[q]);
            acc2[q] = fmaf(lv, w.z, acc2[q]);
        }
    }
    #pragma unroll
    for (int q = 0; q < 4; q++) {
        size_t rr = r0 + q;
        int b = (int)(rr >> 17);
        int s = (int)((rr >> 9) & 255);
        int n = (int)(rr & 511);
        size_t base = ((size_t)(b * 512 + n) * 256 + s) * 96;
        gi[base + lane]      = acc0[q];
        gi[base + lane + 32] = acc1[q];
        gi[base + lane + 64] = acc2[q];
    }
}

// ---------------------------------------------------------------------------
// K4 (R1 version): GRU scan. One warp per (b,n); h in registers + shuffles.
// ---------------------------------------------------------------------------
__global__ __launch_bounds__(256) void k4_gru(
    const float* __restrict__ gi, const float* __restrict__ w_hh,
    const float* __restrict__ b_hh, float* __restrict__ out)
{
    int tid = threadIdx.x, lane = tid & 31;
    int bn = blockIdx.x * 8 + (tid >> 5);
    int b = bn >> 9, n = bn & 511;

    float w0[32], w1[32], w2[32];
    #pragma unroll
    for (int m = 0; m < 8; m++) {
        float4 a = ((const float4*)(w_hh + (size_t)lane * 32))[m];
        float4 c = ((const float4*)(w_hh + (size_t)(lane + 32) * 32))[m];
        float4 d = ((const float4*)(w_hh + (size_t)(lane + 64) * 32))[m];
        w0[4*m+0]=a.x; w0[4*m+1]=a.y; w0[4*m+2]=a.z; w0[4*m+3]=a.w;
        w1[4*m+0]=c.x; w1[4*m+1]=c.y; w1[4*m+2]=c.z; w1[4*m+3]=c.w;
        w2[4*m+0]=d.x; w2[4*m+1]=d.y; w2[4*m+2]=d.z; w2[4*m+3]=d.w;
    }
    float bh0 = b_hh[lane], bh1 = b_hh[lane + 32], bh2 = b_hh[lane + 64];

    float h = 0.f;
    const float* gp = gi + (size_t)bn * 256 * 96;
    for (int t = 0; t < 256; t++, gp += 96) {
        float q0 = gp[lane], q1 = gp[lane + 32], q2 = gp[lane + 64];
        float a0 = bh0, a1 = bh1, a2 = bh2;
        #pragma unroll
        for (int jj = 0; jj < 32; jj++) {
            float hv = __shfl_sync(0xffffffffu, h, jj);
            a0 = fmaf(hv, w0[jj], a0);
            a1 = fmaf(hv, w1[jj], a1);
            a2 = fmaf(hv, w2[jj], a2);
        }
        float rg = sigmoid_f(q0 + a0);
        float zg = sigmoid_f(q1 + a1);
        float ng = tanh_f(fmaf(rg, a2, q2));
        h = fmaf(zg, h - ng, ng);   // (1-z)*n + z*h
        out[((size_t)(b * 256 + t) * 512 + n) * 32 + lane] = h;
    }
}

// ---------------------------------------------------------------------------
extern "C" void kernel_launch(void* const* d_in, const int* in_sizes, int n_in,
                              void* d_out, int out_size)
{
    (void)in_sizes; (void)n_in; (void)out_size;
    const float* x    = (const float*)d_in[0];
    const float* adj  = (const float*)d_in[1];
    const float* W1   = (const float*)d_in[2];
    const float* b1   = (const float*)d_in[3];
    const float* g1   = (const float*)d_in[4];
    const float* be1  = (const float*)d_in[5];
    const float* W2   = (const float*)d_in[6];
    const float* b2   = (const float*)d_in[7];
    const float* g2   = (const float*)d_in[8];
    const float* be2  = (const float*)d_in[9];
    const float* w_ih = (const float*)d_in[10];
    const float* w_hh = (const float*)d_in[11];
    const float* b_ih = (const float*)d_in[12];
    const float* b_hh = (const float*)d_in[13];
    float* out = (float*)d_out;

    float *sp, *th, *gv, *ahi, *alo;
    cudaGetSymbolAddress((void**)&sp,  g_sp);
    cudaGetSymbolAddress((void**)&th,  g_tanh);
    cudaGetSymbolAddress((void**)&gv,  g_gi);
    cudaGetSymbolAddress((void**)&ahi, g_adj_hi);
    cudaGetSymbolAddress((void**)&alo, g_adj_lo);

    static int smem_set = 0;
    if (!smem_set) {
        cudaFuncSetAttribute(k2_mma, cudaFuncAttributeMaxDynamicSharedMemorySize,
                             K2_SMEM_FLOATS * (int)sizeof(float));
        smem_set = 1;
    }

    k0_split<<<(Nn * Nn) / 256, 256>>>(adj, ahi, alo);
    k1_gcn<<<RTOT / 32, 256>>>(x, W1, b1, g1, be1, W2, b2, sp);
    k2_mma<<<dim3(4, BS / 4), 256, K2_SMEM_FLOATS * sizeof(float)>>>(ahi, alo, sp, th);
    k3_ln_gi<<<RTOT / 32, 256>>>(th, g2, be2, w_ih, b_ih, gv);
    k4_gru<<<BN / 8, 256>>>(gv, w_hh, b_hh, out);
}

// round 5
// speedup vs baseline: 1.5087x; 1.1525x over previous
#include <cuda_runtime.h>
#include <math.h>
#include <stdint.h>

// Problem constants
#define Bb   8
#define Ss   256
#define Nn   512
#define Ii   32
#define HH   64
#define Oo   32
#define BS   (Bb*Ss)                 // 2048
#define RTOT (BS*Nn)                 // 1,048,576 rows
#define BN   (Bb*Nn)                 // 4096 GRU sequences

// Scratch (device globals; allocation-free kernel_launch)
__device__ float g_sp  [(size_t)RTOT * Oo];   // 134 MB
__device__ float g_tanh[(size_t)RTOT * Oo];   // 134 MB
__device__ float g_gi  [(size_t)RTOT * 96];   // 402 MB, layout [(b*256+s)*512+n][96]
__device__ float g_adj_hi[Nn * Nn];
__device__ float g_adj_lo[Nn * Nn];

__device__ __forceinline__ float warp_sum(float v) {
    #pragma unroll
    for (int o = 16; o > 0; o >>= 1) v += __shfl_xor_sync(0xffffffffu, v, o);
    return v;
}
__device__ __forceinline__ float sigmoid_f(float x) {
    return __fdividef(1.f, 1.f + __expf(-x));
}
__device__ __forceinline__ float tanh_f(float x) {
    float ax = fabsf(x);
    float e  = __expf(-2.f * ax);
    float t  = (1.f - e) * __fdividef(1.f, 1.f + e);
    return copysignf(t, x);
}
__device__ __forceinline__ float tf32_rna(float v) {
    uint32_t u; asm("cvt.rna.tf32.f32 %0,%1;" : "=r"(u) : "f"(v));
    return __uint_as_float(u);
}
__device__ __forceinline__ uint32_t as_u(float f) { return __float_as_uint(f); }

struct F4 { float x, y, z, w; };
__device__ __forceinline__ void mma_tf32(F4& d,
    uint32_t a0, uint32_t a1, uint32_t a2, uint32_t a3,
    uint32_t b0, uint32_t b1)
{
    asm volatile(
        "mma.sync.aligned.m16n8k8.row.col.f32.tf32.tf32.f32 "
        "{%0,%1,%2,%3},{%4,%5,%6,%7},{%8,%9},{%0,%1,%2,%3};"
        : "+f"(d.x), "+f"(d.y), "+f"(d.z), "+f"(d.w)
        : "r"(a0), "r"(a1), "r"(a2), "r"(a3), "r"(b0), "r"(b1));
}

// ---------------------------------------------------------------------------
// K0: split adj into tf32 hi + fp32 residual
// ---------------------------------------------------------------------------
__global__ __launch_bounds__(256) void k0_split(
    const float* __restrict__ adj, float* __restrict__ hi, float* __restrict__ lo)
{
    int i = blockIdx.x * 256 + threadIdx.x;
    float v = adj[i];
    float h = tf32_rna(v);
    hi[i] = h;
    lo[i] = v - h;
}

// ---------------------------------------------------------------------------
// K1: t = x@W1+b1 ; h = relu(LN64(t)) ; sp = h@W2+b2+x   (R1 version)
// ---------------------------------------------------------------------------
__global__ __launch_bounds__(256) void k1_gcn(
    const float* __restrict__ x,  const float* __restrict__ W1,
    const float* __restrict__ b1, const float* __restrict__ g1,
    const float* __restrict__ be1,const float* __restrict__ W2,
    const float* __restrict__ b2, float* __restrict__ sp_out)
{
    __shared__ __align__(16) float W1p[2048];
    __shared__ __align__(16) float W2p[2048];
    __shared__ float b1s[64], g1s[64], be1s[64], b2s[32];

    int tid = threadIdx.x;
    for (int i = tid; i < 2048; i += 256) {
        int jj = i >> 6, rem = i & 63, j = rem >> 1, p = rem & 1;
        W1p[i] = W1[jj * 64 + j + p * 32];
        W2p[i] = W2[(jj + p * 32) * 32 + j];
    }
    if (tid < 64) { b1s[tid] = b1[tid]; g1s[tid] = g1[tid]; be1s[tid] = be1[tid]; }
    if (tid < 32) b2s[tid] = b2[tid];
    __syncthreads();

    int lane = tid & 31;
    size_t r0 = ((size_t)blockIdx.x * 8 + (tid >> 5)) * 4;

    float xv[4], t0[4], t1[4];
    #pragma unroll
    for (int q = 0; q < 4; q++) {
        xv[q] = x[(r0 + q) * 32 + lane];
        t0[q] = b1s[lane]; t1[q] = b1s[lane + 32];
    }
    #pragma unroll
    for (int jj = 0; jj < 32; jj++) {
        float2 w = *(const float2*)&W1p[jj * 64 + lane * 2];
        #pragma unroll
        for (int q = 0; q < 4; q++) {
            float xb = __shfl_sync(0xffffffffu, xv[q], jj);
            t0[q] = fmaf(xb, w.x, t0[q]);
            t1[q] = fmaf(xb, w.y, t1[q]);
        }
    }
    float h0[4], h1[4];
    #pragma unroll
    for (int q = 0; q < 4; q++) {
        float mu = warp_sum(t0[q] + t1[q]) * (1.f / 64.f);
        float d0 = t0[q] - mu, d1 = t1[q] - mu;
        float var = warp_sum(d0 * d0 + d1 * d1) * (1.f / 64.f);
        float rstd = rsqrtf(var + 1e-5f);
        h0[q] = fmaxf(fmaf(d0 * rstd, g1s[lane],      be1s[lane]),      0.f);
        h1[q] = fmaxf(fmaf(d1 * rstd, g1s[lane + 32], be1s[lane + 32]), 0.f);
    }
    float sp[4];
    #pragma unroll
    for (int q = 0; q < 4; q++) sp[q] = b2s[lane] + xv[q];
    #pragma unroll
    for (int kk = 0; kk < 32; kk++) {
        float2 w = *(const float2*)&W2p[kk * 64 + lane * 2];
        #pragma unroll
        for (int q = 0; q < 4; q++) {
            float a = __shfl_sync(0xffffffffu, h0[q], kk);
            float b = __shfl_sync(0xffffffffu, h1[q], kk);
            sp[q] = fmaf(a, w.x, fmaf(b, w.y, sp[q]));
        }
    }
    #pragma unroll
    for (int q = 0; q < 4; q++) sp_out[(r0 + q) * 32 + lane] = sp[q];
}

// ---------------------------------------------------------------------------
// K2: tf32 MMA adj GEMM, 3-pass compensation (unchanged from R3)
// ---------------------------------------------------------------------------
#define K2_SMEM_FLOATS (2*128*36 + 2*4*32*36)

__global__ __launch_bounds__(256) void k2_mma(
    const float* __restrict__ adj_hi, const float* __restrict__ adj_lo,
    const float* __restrict__ sp, float* __restrict__ out)
{
    extern __shared__ float smem[];
    float* Ah = smem;
    float* Al = Ah + 128 * 36;
    float* Bh = Al + 128 * 36;
    float* Bl = Bh + 4 * 32 * 36;

    int tid  = threadIdx.x, lane = tid & 31, wid = tid >> 5;
    int n0   = blockIdx.x * 128;
    int bs0  = blockIdx.y * 4;
    int mbase = wid * 16;
    int r = lane >> 2, c = lane & 3;

    F4 acc[4][4];
    #pragma unroll
    for (int u = 0; u < 4; u++)
        #pragma unroll
        for (int j = 0; j < 4; j++) { acc[u][j].x = acc[u][j].y = acc[u][j].z = acc[u][j].w = 0.f; }

    for (int mc = 0; mc < 512; mc += 32) {
        __syncthreads();
        #pragma unroll
        for (int i = 0; i < 4; i++) {
            int q = i * 256 + tid;
            int n = q >> 3, k4 = (q & 7) * 4;
            size_t g = (size_t)(n0 + n) * 512 + mc + k4;
            *(float4*)&Ah[n * 36 + k4] = *(const float4*)&adj_hi[g];
            *(float4*)&Al[n * 36 + k4] = *(const float4*)&adj_lo[g];
        }
        {
            int k = tid >> 3, f4 = (tid & 7) * 4;
            #pragma unroll
            for (int u = 0; u < 4; u++) {
                float4 v = *(const float4*)&sp[((size_t)(bs0 + u) * 512 + mc + k) * 32 + f4];
                float hx = tf32_rna(v.x), hy = tf32_rna(v.y);
                float hz = tf32_rna(v.z), hw = tf32_rna(v.w);
                float4 hv = { hx, hy, hz, hw };
                float4 lv = { v.x - hx, v.y - hy, v.z - hz, v.w - hw };
                *(float4*)&Bh[(u * 32 + k) * 36 + f4] = hv;
                *(float4*)&Bl[(u * 32 + k) * 36 + f4] = lv;
            }
        }
        __syncthreads();

        #pragma unroll
        for (int kt = 0; kt < 4; kt++) {
            int kb = kt * 8;
            uint32_t ah0 = as_u(Ah[(mbase + r)     * 36 + kb + c]);
            uint32_t ah1 = as_u(Ah[(mbase + 8 + r) * 36 + kb + c]);
            uint32_t ah2 = as_u(Ah[(mbase + r)     * 36 + kb + 4 + c]);
            uint32_t ah3 = as_u(Ah[(mbase + 8 + r) * 36 + kb + 4 + c]);
            uint32_t al0 = as_u(Al[(mbase + r)     * 36 + kb + c]);
            uint32_t al1 = as_u(Al[(mbase + 8 + r) * 36 + kb + c]);
            uint32_t al2 = as_u(Al[(mbase + r)     * 36 + kb + 4 + c]);
            uint32_t al3 = as_u(Al[(mbase + 8 + r) * 36 + kb + 4 + c]);
            #pragma unroll
            for (int u = 0; u < 4; u++) {
                #pragma unroll
                for (int j = 0; j < 4; j++) {
                    uint32_t bh0 = as_u(Bh[(u * 32 + kb + c)     * 36 + j * 8 + r]);
                    uint32_t bh1 = as_u(Bh[(u * 32 + kb + 4 + c) * 36 + j * 8 + r]);
                    uint32_t bl0 = as_u(Bl[(u * 32 + kb + c)     * 36 + j * 8 + r]);
                    uint32_t bl1 = as_u(Bl[(u * 32 + kb + 4 + c) * 36 + j * 8 + r]);
                    mma_tf32(acc[u][j], ah0, ah1, ah2, ah3, bh0, bh1);
                    mma_tf32(acc[u][j], al0, al1, al2, al3, bh0, bh1);
                    mma_tf32(acc[u][j], ah0, ah1, ah2, ah3, bl0, bl1);
                }
            }
        }
    }

    int c2 = (lane & 3) * 2;
    #pragma unroll
    for (int u = 0; u < 4; u++) {
        size_t bsrow = (size_t)(bs0 + u) * 512;
        #pragma unroll
        for (int j = 0; j < 4; j++) {
            int col  = j * 8 + c2;
            int row0 = n0 + mbase + r;
            float2 v0 = { tanh_f(acc[u][j].x), tanh_f(acc[u][j].y) };
            float2 v1 = { tanh_f(acc[u][j].z), tanh_f(acc[u][j].w) };
            *(float2*)&out[(bsrow + row0)     * 32 + col] = v0;
            *(float2*)&out[(bsrow + row0 + 8) * 32 + col] = v1;
        }
    }
}

// ---------------------------------------------------------------------------
// K3 (NEW): LN32 per row + tf32 MMA: gi = ln @ w_ih^T + b_ih.
// Block handles 128 rows. A = ln (hi/lo, [128][36]), B = w_ih^T (hi/lo,
// [32][104] -> conflict-free frag reads). Single K=32 pass, 3 mma passes.
// gi layout: row-major [(b*256+s)*512+n][96].
// ---------------------------------------------------------------------------
#define K3_SMEM_FLOATS (2*128*36 + 2*32*104 + 96)

__global__ __launch_bounds__(256) void k3_mma(
    const float* __restrict__ tin, const float* __restrict__ g2,
    const float* __restrict__ be2, const float* __restrict__ w_ih,
    const float* __restrict__ b_ih, float* __restrict__ gi)
{
    extern __shared__ float smem[];
    float* Ah  = smem;                 // [128][36]
    float* Al  = Ah + 128 * 36;
    float* Bh  = Al + 128 * 36;        // [32][104]
    float* Bl  = Bh + 32 * 104;
    float* bis = Bl + 32 * 104;        // [96]

    int tid = threadIdx.x, lane = tid & 31, wid = tid >> 5;
    size_t rr0 = (size_t)blockIdx.x * 128;

    // stage B: w_ih[o][j] -> B[j][o], tf32 split
    #pragma unroll
    for (int p = 0; p < 12; p++) {
        int idx = p * 256 + tid;            // 0..3071
        int o = idx >> 5, j = idx & 31;
        float v = w_ih[idx];
        float h = tf32_rna(v);
        Bh[j * 104 + o] = h;
        Bl[j * 104 + o] = v - h;
    }
    if (tid < 96) bis[tid] = b_ih[tid];

    // LN per row -> A tiles. Warp wid handles rows wid*16 .. wid*16+15.
    float g2v = g2[lane], be2v = be2[lane];
    #pragma unroll
    for (int q = 0; q < 16; q++) {
        int row = wid * 16 + q;
        float v = tin[(rr0 + row) * 32 + lane];
        float mu = warp_sum(v) * (1.f / 32.f);
        float d = v - mu;
        float var = warp_sum(d * d) * (1.f / 32.f);
        float ln = fmaf(d * rsqrtf(var + 1e-5f), g2v, be2v);
        float lh = tf32_rna(ln);
        Ah[row * 36 + lane] = lh;
        Al[row * 36 + lane] = ln - lh;
    }
    __syncthreads();

    // MMA: per warp one m-tile of 16 rows; N=96 -> 12 n-tiles; K=32 -> 4 kt.
    int r = lane >> 2, c = lane & 3;
    int mbase = wid * 16;
    F4 acc[12];
    #pragma unroll
    for (int j = 0; j < 12; j++) { acc[j].x = acc[j].y = acc[j].z = acc[j].w = 0.f; }

    #pragma unroll
    for (int kt = 0; kt < 4; kt++) {
        int kb = kt * 8;
        uint32_t ah0 = as_u(Ah[(mbase + r)     * 36 + kb + c]);
        uint32_t ah1 = as_u(Ah[(mbase + 8 + r) * 36 + kb + c]);
        uint32_t ah2 = as_u(Ah[(mbase + r)     * 36 + kb + 4 + c]);
        uint32_t ah3 = as_u(Ah[(mbase + 8 + r) * 36 + kb + 4 + c]);
        uint32_t al0 = as_u(Al[(mbase + r)     * 36 + kb + c]);
        uint32_t al1 = as_u(Al[(mbase + 8 + r) * 36 + kb + c]);
        uint32_t al2 = as_u(Al[(mbase + r)     * 36 + kb + 4 + c]);
        uint32_t al3 = as_u(Al[(mbase + 8 + r) * 36 + kb + 4 + c]);
        #pragma unroll
        for (int j = 0; j < 12; j++) {
            uint32_t bh0 = as_u(Bh[(kb + c)     * 104 + j * 8 + r]);
            uint32_t bh1 = as_u(Bh[(kb + 4 + c) * 104 + j * 8 + r]);
            uint32_t bl0 = as_u(Bl[(kb + c)     * 104 + j * 8 + r]);
            uint32_t bl1 = as_u(Bl[(kb + 4 + c) * 104 + j * 8 + r]);
            mma_tf32(acc[j], ah0, ah1, ah2, ah3, bh0, bh1);
            mma_tf32(acc[j], al0, al1, al2, al3, bh0, bh1);
            mma_tf32(acc[j], ah0, ah1, ah2, ah3, bl0, bl1);
        }
    }

    // epilogue: + b_ih, store float2 frags (rows contiguous 96-float records)
    int c2 = (lane & 3) * 2;
    #pragma unroll
    for (int j = 0; j < 12; j++) {
        int col = j * 8 + c2;
        float2 bi = *(const float2*)&bis[col];
        size_t row0 = rr0 + mbase + r;
        float2 v0 = { acc[j].x + bi.x, acc[j].y + bi.y };
        float2 v1 = { acc[j].z + bi.x, acc[j].w + bi.y };
        *(float2*)&gi[row0 * 96 + col]       = v0;
        *(float2*)&gi[(row0 + 8) * 96 + col] = v1;
    }
}

// ---------------------------------------------------------------------------
// K4: GRU scan. One warp per (b,n); h in registers + shuffles; split 16+16
// accumulator chains for 2x ILP; next-step gi prefetch.
// gi layout: [(b*256+t)*512+n][96].
// ---------------------------------------------------------------------------
__global__ __launch_bounds__(256) void k4_gru(
    const float* __restrict__ gi, const float* __restrict__ w_hh,
    const float* __restrict__ b_hh, float* __restrict__ out)
{
    int tid = threadIdx.x, lane = tid & 31;
    int bn = blockIdx.x * 8 + (tid >> 5);
    int b = bn >> 9, n = bn & 511;

    float w0[32], w1[32], w2[32];
    #pragma unroll
    for (int m = 0; m < 8; m++) {
        float4 a = ((const float4*)(w_hh + (size_t)lane * 32))[m];
        float4 c = ((const float4*)(w_hh + (size_t)(lane + 32) * 32))[m];
        float4 d = ((const float4*)(w_hh + (size_t)(lane + 64) * 32))[m];
        w0[4*m+0]=a.x; w0[4*m+1]=a.y; w0[4*m+2]=a.z; w0[4*m+3]=a.w;
        w1[4*m+0]=c.x; w1[4*m+1]=c.y; w1[4*m+2]=c.z; w1[4*m+3]=c.w;
        w2[4*m+0]=d.x; w2[4*m+1]=d.y; w2[4*m+2]=d.z; w2[4*m+3]=d.w;
    }
    float bh0 = b_hh[lane], bh1 = b_hh[lane + 32], bh2 = b_hh[lane + 64];

    float h = 0.f;
    const size_t stride = (size_t)512 * 96;
    const float* gp = gi + ((size_t)(b * 256) * 512 + n) * 96;
    float q0 = gp[lane], q1 = gp[lane + 32], q2 = gp[lane + 64];

    for (int t = 0; t < 256; t++) {
        const float* gn = gp + ((t < 255) ? stride : 0);
        float p0 = gn[lane], p1 = gn[lane + 32], p2 = gn[lane + 64];

        float a0 = bh0, a1 = bh1, a2 = bh2;
        float e0 = 0.f, e1 = 0.f, e2 = 0.f;
        #pragma unroll
        for (int jj = 0; jj < 16; jj++) {
            float hv = __shfl_sync(0xffffffffu, h, jj);
            float hw = __shfl_sync(0xffffffffu, h, jj + 16);
            a0 = fmaf(hv, w0[jj], a0);
            e0 = fmaf(hw, w0[jj + 16], e0);
            a1 = fmaf(hv, w1[jj], a1);
            e1 = fmaf(hw, w1[jj + 16], e1);
            a2 = fmaf(hv, w2[jj], a2);
            e2 = fmaf(hw, w2[jj + 16], e2);
        }
        a0 += e0; a1 += e1; a2 += e2;

        float rg = sigmoid_f(q0 + a0);
        float zg = sigmoid_f(q1 + a1);
        float ng = tanh_f(fmaf(rg, a2, q2));
        h = fmaf(zg, h - ng, ng);
        out[((size_t)(b * 256 + t) * 512 + n) * 32 + lane] = h;

        gp = gn; q0 = p0; q1 = p1; q2 = p2;
    }
}

// ---------------------------------------------------------------------------
extern "C" void kernel_launch(void* const* d_in, const int* in_sizes, int n_in,
                              void* d_out, int out_size)
{
    (void)in_sizes; (void)n_in; (void)out_size;
    const float* x    = (const float*)d_in[0];
    const float* adj  = (const float*)d_in[1];
    const float* W1   = (const float*)d_in[2];
    const float* b1   = (const float*)d_in[3];
    const float* g1   = (const float*)d_in[4];
    const float* be1  = (const float*)d_in[5];
    const float* W2   = (const float*)d_in[6];
    const float* b2   = (const float*)d_in[7];
    const float* g2   = (const float*)d_in[8];
    const float* be2  = (const float*)d_in[9];
    const float* w_ih = (const float*)d_in[10];
    const float* w_hh = (const float*)d_in[11];
    const float* b_ih = (const float*)d_in[12];
    const float* b_hh = (const float*)d_in[13];
    float* out = (float*)d_out;

    float *sp, *th, *gv, *ahi, *alo;
    cudaGetSymbolAddress((void**)&sp,  g_sp);
    cudaGetSymbolAddress((void**)&th,  g_tanh);
    cudaGetSymbolAddress((void**)&gv,  g_gi);
    cudaGetSymbolAddress((void**)&ahi, g_adj_hi);
    cudaGetSymbolAddress((void**)&alo, g_adj_lo);

    static int smem_set = 0;
    if (!smem_set) {
        cudaFuncSetAttribute(k2_mma, cudaFuncAttributeMaxDynamicSharedMemorySize,
                             K2_SMEM_FLOATS * (int)sizeof(float));
        cudaFuncSetAttribute(k3_mma, cudaFuncAttributeMaxDynamicSharedMemorySize,
                             K3_SMEM_FLOATS * (int)sizeof(float));
        smem_set = 1;
    }

    k0_split<<<(Nn * Nn) / 256, 256>>>(adj, ahi, alo);
    k1_gcn<<<RTOT / 32, 256>>>(x, W1, b1, g1, be1, W2, b2, sp);
    k2_mma<<<dim3(4, BS / 4), 256, K2_SMEM_FLOATS * sizeof(float)>>>(ahi, alo, sp, th);
    k3_mma<<<RTOT / 128, 256, K3_SMEM_FLOATS * sizeof(float)>>>(th, g2, be2, w_ih, b_ih, gv);
    k4_gru<<<BN / 8, 256>>>(gv, w_hh, b_hh, out);
}

// round 6
// speedup vs baseline: 1.5970x; 1.0586x over previous
#include <cuda_runtime.h>
#include <math.h>
#include <stdint.h>

// Problem constants
#define Bb   8
#define Ss   256
#define Nn   512
#define Ii   32
#define HH   64
#define Oo   32
#define BS   (Bb*Ss)                 // 2048
#define RTOT (BS*Nn)                 // 1,048,576 rows
#define BN   (Bb*Nn)                 // 4096 GRU sequences

// Scratch (device globals; allocation-free kernel_launch)
__device__ float g_sp  [(size_t)RTOT * Oo];   // 134 MB
__device__ float g_tanh[(size_t)RTOT * Oo];   // 134 MB
__device__ float g_gi  [(size_t)RTOT * 96];   // 402 MB, layout [(b*256+s)*512+n][96]
__device__ float g_adj_hi[Nn * Nn];
__device__ float g_adj_lo[Nn * Nn];

__device__ __forceinline__ float warp_sum(float v) {
    #pragma unroll
    for (int o = 16; o > 0; o >>= 1) v += __shfl_xor_sync(0xffffffffu, v, o);
    return v;
}
__device__ __forceinline__ float sigmoid_f(float x) {
    return __fdividef(1.f, 1.f + __expf(-x));
}
__device__ __forceinline__ float tanh_f(float x) {
    float ax = fabsf(x);
    float e  = __expf(-2.f * ax);
    float t  = (1.f - e) * __fdividef(1.f, 1.f + e);
    return copysignf(t, x);
}
__device__ __forceinline__ float tf32_rna(float v) {
    uint32_t u; asm("cvt.rna.tf32.f32 %0,%1;" : "=r"(u) : "f"(v));
    return __uint_as_float(u);
}
__device__ __forceinline__ uint32_t as_u(float f) { return __float_as_uint(f); }

struct F4 { float x, y, z, w; };
__device__ __forceinline__ void mma_tf32(F4& d,
    uint32_t a0, uint32_t a1, uint32_t a2, uint32_t a3,
    uint32_t b0, uint32_t b1)
{
    asm volatile(
        "mma.sync.aligned.m16n8k8.row.col.f32.tf32.tf32.f32 "
        "{%0,%1,%2,%3},{%4,%5,%6,%7},{%8,%9},{%0,%1,%2,%3};"
        : "+f"(d.x), "+f"(d.y), "+f"(d.z), "+f"(d.w)
        : "r"(a0), "r"(a1), "r"(a2), "r"(a3), "r"(b0), "r"(b1));
}

__device__ __forceinline__ void cp4(uint32_t dst, const float* src) {
    asm volatile("cp.async.ca.shared.global [%0], [%1], 4;" :: "r"(dst), "l"(src));
}

// ---------------------------------------------------------------------------
// K0: split adj into tf32 hi + fp32 residual
// ---------------------------------------------------------------------------
__global__ __launch_bounds__(256) void k0_split(
    const float* __restrict__ adj, float* __restrict__ hi, float* __restrict__ lo)
{
    int i = blockIdx.x * 256 + threadIdx.x;
    float v = adj[i];
    float h = tf32_rna(v);
    hi[i] = h;
    lo[i] = v - h;
}

// ---------------------------------------------------------------------------
// K1: t = x@W1+b1 ; h = relu(LN64(t)) ; sp = h@W2+b2+x
// ---------------------------------------------------------------------------
__global__ __launch_bounds__(256) void k1_gcn(
    const float* __restrict__ x,  const float* __restrict__ W1,
    const float* __restrict__ b1, const float* __restrict__ g1,
    const float* __restrict__ be1,const float* __restrict__ W2,
    const float* __restrict__ b2, float* __restrict__ sp_out)
{
    __shared__ __align__(16) float W1p[2048];
    __shared__ __align__(16) float W2p[2048];
    __shared__ float b1s[64], g1s[64], be1s[64], b2s[32];

    int tid = threadIdx.x;
    for (int i = tid; i < 2048; i += 256) {
        int jj = i >> 6, rem = i & 63, j = rem >> 1, p = rem & 1;
        W1p[i] = W1[jj * 64 + j + p * 32];
        W2p[i] = W2[(jj + p * 32) * 32 + j];
    }
    if (tid < 64) { b1s[tid] = b1[tid]; g1s[tid] = g1[tid]; be1s[tid] = be1[tid]; }
    if (tid < 32) b2s[tid] = b2[tid];
    __syncthreads();

    int lane = tid & 31;
    size_t r0 = ((size_t)blockIdx.x * 8 + (tid >> 5)) * 4;

    float xv[4], t0[4], t1[4];
    #pragma unroll
    for (int q = 0; q < 4; q++) {
        xv[q] = x[(r0 + q) * 32 + lane];
        t0[q] = b1s[lane]; t1[q] = b1s[lane + 32];
    }
    #pragma unroll
    for (int jj = 0; jj < 32; jj++) {
        float2 w = *(const float2*)&W1p[jj * 64 + lane * 2];
        #pragma unroll
        for (int q = 0; q < 4; q++) {
            float xb = __shfl_sync(0xffffffffu, xv[q], jj);
            t0[q] = fmaf(xb, w.x, t0[q]);
            t1[q] = fmaf(xb, w.y, t1[q]);
        }
    }
    float h0[4], h1[4];
    #pragma unroll
    for (int q = 0; q < 4; q++) {
        float mu = warp_sum(t0[q] + t1[q]) * (1.f / 64.f);
        float d0 = t0[q] - mu, d1 = t1[q] - mu;
        float var = warp_sum(d0 * d0 + d1 * d1) * (1.f / 64.f);
        float rstd = rsqrtf(var + 1e-5f);
        h0[q] = fmaxf(fmaf(d0 * rstd, g1s[lane],      be1s[lane]),      0.f);
        h1[q] = fmaxf(fmaf(d1 * rstd, g1s[lane + 32], be1s[lane + 32]), 0.f);
    }
    float sp[4];
    #pragma unroll
    for (int q = 0; q < 4; q++) sp[q] = b2s[lane] + xv[q];
    #pragma unroll
    for (int kk = 0; kk < 32; kk++) {
        float2 w = *(const float2*)&W2p[kk * 64 + lane * 2];
        #pragma unroll
        for (int q = 0; q < 4; q++) {
            float a = __shfl_sync(0xffffffffu, h0[q], kk);
            float b = __shfl_sync(0xffffffffu, h1[q], kk);
            sp[q] = fmaf(a, w.x, fmaf(b, w.y, sp[q]));
        }
    }
    #pragma unroll
    for (int q = 0; q < 4; q++) sp_out[(r0 + q) * 32 + lane] = sp[q];
}

// ---------------------------------------------------------------------------
// K2: tf32 MMA adj GEMM, 3-pass compensation.
// NEW: fragment-major smem layouts -> all mainloop fragment loads are
// conflict-free LDS.128.
//   A: Ah[(w*4+kt)*128 + lane*4 + reg]            (reg = a0..a3)
//   B: Bh[((u*4+kt)*2+half)*160 + c*40 + r*4 + j] (c-stride 40: conflict-free)
// ---------------------------------------------------------------------------
#define K2_SMEM_FLOATS (2*4096 + 2*5120)   // 18432 floats = 73728 B

__global__ __launch_bounds__(256) void k2_mma(
    const float* __restrict__ adj_hi, const float* __restrict__ adj_lo,
    const float* __restrict__ sp, float* __restrict__ out)
{
    extern __shared__ float smem[];
    float* Ah = smem;
    float* Al = Ah + 4096;
    float* Bh = Al + 4096;
    float* Bl = Bh + 5120;

    int tid  = threadIdx.x, lane = tid & 31, wid = tid >> 5;
    int n0   = blockIdx.x * 128;
    int bs0  = blockIdx.y * 4;
    int mbase = wid * 16;
    int r = lane >> 2, c = lane & 3;

    F4 acc[4][4];
    #pragma unroll
    for (int u = 0; u < 4; u++)
        #pragma unroll
        for (int j = 0; j < 4; j++) { acc[u][j].x = acc[u][j].y = acc[u][j].z = acc[u][j].w = 0.f; }

    // B staging decomposition for this thread (constant across chunks)
    int sk = tid >> 3, sf4 = (tid & 7) * 4;
    int skt = sk >> 3, shalf = (sk >> 2) & 1, scc = sk & 3;
    int sj = sf4 >> 3, sr0 = sf4 & 7;

    for (int mc = 0; mc < 512; mc += 32) {
        __syncthreads();
        // stage A (adj hi/lo) in fragment order
        #pragma unroll
        for (int i = 0; i < 4; i++) {
            int idx = i * 256 + tid;          // 0..1023
            int n = idx >> 3, k4 = (idx & 7) * 4;
            size_t g = (size_t)(n0 + n) * 512 + mc + k4;
            float4 vh = *(const float4*)&adj_hi[g];
            float4 vl = *(const float4*)&adj_lo[g];
            int w = n >> 4, rr = n & 15;
            int base = (w * 4 + (k4 >> 3)) * 128 + (rr & 7) * 16
                     + ((k4 >> 2) & 1) * 2 + (rr >> 3);
            Ah[base + 0] = vh.x; Ah[base + 4] = vh.y; Ah[base + 8] = vh.z; Ah[base + 12] = vh.w;
            Al[base + 0] = vl.x; Al[base + 4] = vl.y; Al[base + 8] = vl.z; Al[base + 12] = vl.w;
        }
        // stage B (sp, tf32-split) in fragment order
        {
            int bbase = ((0 * 4 + skt) * 2 + shalf) * 160 + scc * 40 + sr0 * 4 + sj;
            #pragma unroll
            for (int u = 0; u < 4; u++) {
                float4 v = *(const float4*)&sp[((size_t)(bs0 + u) * 512 + mc + sk) * 32 + sf4];
                float hx = tf32_rna(v.x), hy = tf32_rna(v.y);
                float hz = tf32_rna(v.z), hw = tf32_rna(v.w);
                int bo = bbase + u * (4 * 2 * 160);
                Bh[bo + 0] = hx; Bh[bo + 4] = hy; Bh[bo + 8] = hz; Bh[bo + 12] = hw;
                Bl[bo + 0] = v.x - hx; Bl[bo + 4] = v.y - hy;
                Bl[bo + 8] = v.z - hz; Bl[bo + 12] = v.w - hw;
            }
        }
        __syncthreads();

        #pragma unroll
        for (int kt = 0; kt < 4; kt++) {
            float ah[4], al[4];
            *(float4*)ah = *(const float4*)&Ah[(wid * 4 + kt) * 128 + lane * 4];
            *(float4*)al = *(const float4*)&Al[(wid * 4 + kt) * 128 + lane * 4];
            uint32_t ah0 = as_u(ah[0]), ah1 = as_u(ah[1]), ah2 = as_u(ah[2]), ah3 = as_u(ah[3]);
            uint32_t al0 = as_u(al[0]), al1 = as_u(al[1]), al2 = as_u(al[2]), al3 = as_u(al[3]);
            #pragma unroll
            for (int u = 0; u < 4; u++) {
                int bb = (u * 4 + kt) * 2 * 160 + c * 40 + r * 4;
                float bh0[4], bh1[4], bl0[4], bl1[4];
                *(float4*)bh0 = *(const float4*)&Bh[bb];
                *(float4*)bh1 = *(const float4*)&Bh[bb + 160];
                *(float4*)bl0 = *(const float4*)&Bl[bb];
                *(float4*)bl1 = *(const float4*)&Bl[bb + 160];
                #pragma unroll
                for (int j = 0; j < 4; j++) {
                    mma_tf32(acc[u][j], ah0, ah1, ah2, ah3, as_u(bh0[j]), as_u(bh1[j]));
                    mma_tf32(acc[u][j], al0, al1, al2, al3, as_u(bh0[j]), as_u(bh1[j]));
                    mma_tf32(acc[u][j], ah0, ah1, ah2, ah3, as_u(bl0[j]), as_u(bl1[j]));
                }
            }
        }
    }

    int c2 = (lane & 3) * 2;
    #pragma unroll
    for (int u = 0; u < 4; u++) {
        size_t bsrow = (size_t)(bs0 + u) * 512;
        #pragma unroll
        for (int j = 0; j < 4; j++) {
            int col  = j * 8 + c2;
            int row0 = n0 + mbase + r;
            float2 v0 = { tanh_f(acc[u][j].x), tanh_f(acc[u][j].y) };
            float2 v1 = { tanh_f(acc[u][j].z), tanh_f(acc[u][j].w) };
            *(float2*)&out[(bsrow + row0)     * 32 + col] = v0;
            *(float2*)&out[(bsrow + row0 + 8) * 32 + col] = v1;
        }
    }
}

// ---------------------------------------------------------------------------
// K3: LN32 per row + tf32 MMA: gi = ln @ w_ih^T + b_ih. (unchanged)
// ---------------------------------------------------------------------------
#define K3_SMEM_FLOATS (2*128*36 + 2*32*104 + 96)

__global__ __launch_bounds__(256) void k3_mma(
    const float* __restrict__ tin, const float* __restrict__ g2,
    const float* __restrict__ be2, const float* __restrict__ w_ih,
    const float* __restrict__ b_ih, float* __restrict__ gi)
{
    extern __shared__ float smem[];
    float* Ah  = smem;                 // [128][36]
    float* Al  = Ah + 128 * 36;
    float* Bh  = Al + 128 * 36;        // [32][104]
    float* Bl  = Bh + 32 * 104;
    float* bis = Bl + 32 * 104;        // [96]

    int tid = threadIdx.x, lane = tid & 31, wid = tid >> 5;
    size_t rr0 = (size_t)blockIdx.x * 128;

    #pragma unroll
    for (int p = 0; p < 12; p++) {
        int idx = p * 256 + tid;
        int o = idx >> 5, j = idx & 31;
        float v = w_ih[idx];
        float h = tf32_rna(v);
        Bh[j * 104 + o] = h;
        Bl[j * 104 + o] = v - h;
    }
    if (tid < 96) bis[tid] = b_ih[tid];

    float g2v = g2[lane], be2v = be2[lane];
    #pragma unroll
    for (int q = 0; q < 16; q++) {
        int row = wid * 16 + q;
        float v = tin[(rr0 + row) * 32 + lane];
        float mu = warp_sum(v) * (1.f / 32.f);
        float d = v - mu;
        float var = warp_sum(d * d) * (1.f / 32.f);
        float ln = fmaf(d * rsqrtf(var + 1e-5f), g2v, be2v);
        float lh = tf32_rna(ln);
        Ah[row * 36 + lane] = lh;
        Al[row * 36 + lane] = ln - lh;
    }
    __syncthreads();

    int r = lane >> 2, c = lane & 3;
    int mbase = wid * 16;
    F4 acc[12];
    #pragma unroll
    for (int j = 0; j < 12; j++) { acc[j].x = acc[j].y = acc[j].z = acc[j].w = 0.f; }

    #pragma unroll
    for (int kt = 0; kt < 4; kt++) {
        int kb = kt * 8;
        uint32_t ah0 = as_u(Ah[(mbase + r)     * 36 + kb + c]);
        uint32_t ah1 = as_u(Ah[(mbase + 8 + r) * 36 + kb + c]);
        uint32_t ah2 = as_u(Ah[(mbase + r)     * 36 + kb + 4 + c]);
        uint32_t ah3 = as_u(Ah[(mbase + 8 + r) * 36 + kb + 4 + c]);
        uint32_t al0 = as_u(Al[(mbase + r)     * 36 + kb + c]);
        uint32_t al1 = as_u(Al[(mbase + 8 + r) * 36 + kb + c]);
        uint32_t al2 = as_u(Al[(mbase + r)     * 36 + kb + 4 + c]);
        uint32_t al3 = as_u(Al[(mbase + 8 + r) * 36 + kb + 4 + c]);
        #pragma unroll
        for (int j = 0; j < 12; j++) {
            uint32_t bh0 = as_u(Bh[(kb + c)     * 104 + j * 8 + r]);
            uint32_t bh1 = as_u(Bh[(kb + 4 + c) * 104 + j * 8 + r]);
            uint32_t bl0 = as_u(Bl[(kb + c)     * 104 + j * 8 + r]);
            uint32_t bl1 = as_u(Bl[(kb + 4 + c) * 104 + j * 8 + r]);
            mma_tf32(acc[j], ah0, ah1, ah2, ah3, bh0, bh1);
            mma_tf32(acc[j], al0, al1, al2, al3, bh0, bh1);
            mma_tf32(acc[j], ah0, ah1, ah2, ah3, bl0, bl1);
        }
    }

    int c2 = (lane & 3) * 2;
    #pragma unroll
    for (int j = 0; j < 12; j++) {
        int col = j * 8 + c2;
        float2 bi = *(const float2*)&bis[col];
        size_t row0 = rr0 + mbase + r;
        float2 v0 = { acc[j].x + bi.x, acc[j].y + bi.y };
        float2 v1 = { acc[j].z + bi.x, acc[j].w + bi.y };
        *(float2*)&gi[row0 * 96 + col]       = v0;
        *(float2*)&gi[(row0 + 8) * 96 + col] = v1;
    }
}

// ---------------------------------------------------------------------------
// K4: GRU scan. One warp per (b,n). NEW: 8-stage cp.async smem ring for gi
// (zero register cost, MLP=24/warp); gate GEMV split 16+16 for ILP.
// ---------------------------------------------------------------------------
__global__ __launch_bounds__(256) void k4_gru(
    const float* __restrict__ gi, const float* __restrict__ w_hh,
    const float* __restrict__ b_hh, float* __restrict__ out)
{
    __shared__ float gbuf[8][8][96];   // [warp][stage][96 gates]

    int tid = threadIdx.x, lane = tid & 31, wr = tid >> 5;
    int bn = blockIdx.x * 8 + wr;
    int b = bn >> 9, n = bn & 511;

    float w0[32], w1[32], w2[32];
    #pragma unroll
    for (int m = 0; m < 8; m++) {
        float4 a = ((const float4*)(w_hh + (size_t)lane * 32))[m];
        float4 c = ((const float4*)(w_hh + (size_t)(lane + 32) * 32))[m];
        float4 d = ((const float4*)(w_hh + (size_t)(lane + 64) * 32))[m];
        w0[4*m+0]=a.x; w0[4*m+1]=a.y; w0[4*m+2]=a.z; w0[4*m+3]=a.w;
        w1[4*m+0]=c.x; w1[4*m+1]=c.y; w1[4*m+2]=c.z; w1[4*m+3]=c.w;
        w2[4*m+0]=d.x; w2[4*m+1]=d.y; w2[4*m+2]=d.z; w2[4*m+3]=d.w;
    }
    float bh0 = b_hh[lane], bh1 = b_hh[lane + 32], bh2 = b_hh[lane + 64];

    const size_t tstride = (size_t)512 * 96;
    const float* gbase = gi + ((size_t)(b * 256) * 512 + n) * 96;

    // preamble: stages 0..6 in flight
    #pragma unroll
    for (int s = 0; s < 7; s++) {
        const float* src = gbase + (size_t)s * tstride;
        uint32_t d = (uint32_t)__cvta_generic_to_shared(&gbuf[wr][s][lane]);
        cp4(d, src + lane);
        cp4(d + 128, src + lane + 32);
        cp4(d + 256, src + lane + 64);
        asm volatile("cp.async.commit_group;" ::: "memory");
    }

    float h = 0.f;
    for (int t = 0; t < 256; t++) {
        if (t + 7 < 256) {
            const float* src = gbase + (size_t)(t + 7) * tstride;
            uint32_t d = (uint32_t)__cvta_generic_to_shared(&gbuf[wr][(t + 7) & 7][lane]);
            cp4(d, src + lane);
            cp4(d + 128, src + lane + 32);
            cp4(d + 256, src + lane + 64);
        }
        asm volatile("cp.async.commit_group;" ::: "memory");
        asm volatile("cp.async.wait_group 7;" ::: "memory");

        int s = t & 7;
        float q0 = gbuf[wr][s][lane];
        float q1 = gbuf[wr][s][lane + 32];
        float q2 = gbuf[wr][s][lane + 64];

        float a0 = bh0, a1 = bh1, a2 = bh2;
        float e0 = 0.f, e1 = 0.f, e2 = 0.f;
        #pragma unroll
        for (int jj = 0; jj < 16; jj++) {
            float hv = __shfl_sync(0xffffffffu, h, jj);
            float hw = __shfl_sync(0xffffffffu, h, jj + 16);
            a0 = fmaf(hv, w0[jj], a0);
            e0 = fmaf(hw, w0[jj + 16], e0);
            a1 = fmaf(hv, w1[jj], a1);
            e1 = fmaf(hw, w1[jj + 16], e1);
            a2 = fmaf(hv, w2[jj], a2);
            e2 = fmaf(hw, w2[jj + 16], e2);
        }
        a0 += e0; a1 += e1; a2 += e2;

        float rg = sigmoid_f(q0 + a0);
        float zg = sigmoid_f(q1 + a1);
        float ng = tanh_f(fmaf(rg, a2, q2));
        h = fmaf(zg, h - ng, ng);
        out[((size_t)(b * 256 + t) * 512 + n) * 32 + lane] = h;
    }
}

// ---------------------------------------------------------------------------
extern "C" void kernel_launch(void* const* d_in, const int* in_sizes, int n_in,
                              void* d_out, int out_size)
{
    (void)in_sizes; (void)n_in; (void)out_size;
    const float* x    = (const float*)d_in[0];
    const float* adj  = (const float*)d_in[1];
    const float* W1   = (const float*)d_in[2];
    const float* b1   = (const float*)d_in[3];
    const float* g1   = (const float*)d_in[4];
    const float* be1  = (const float*)d_in[5];
    const float* W2   = (const float*)d_in[6];
    const float* b2   = (const float*)d_in[7];
    const float* g2   = (const float*)d_in[8];
    const float* be2  = (const float*)d_in[9];
    const float* w_ih = (const float*)d_in[10];
    const float* w_hh = (const float*)d_in[11];
    const float* b_ih = (const float*)d_in[12];
    const float* b_hh = (const float*)d_in[13];
    float* out = (float*)d_out;

    float *sp, *th, *gv, *ahi, *alo;
    cudaGetSymbolAddress((void**)&sp,  g_sp);
    cudaGetSymbolAddress((void**)&th,  g_tanh);
    cudaGetSymbolAddress((void**)&gv,  g_gi);
    cudaGetSymbolAddress((void**)&ahi, g_adj_hi);
    cudaGetSymbolAddress((void**)&alo, g_adj_lo);

    static int smem_set = 0;
    if (!smem_set) {
        cudaFuncSetAttribute(k2_mma, cudaFuncAttributeMaxDynamicSharedMemorySize,
                             K2_SMEM_FLOATS * (int)sizeof(float));
        cudaFuncSetAttribute(k3_mma, cudaFuncAttributeMaxDynamicSharedMemorySize,
                             K3_SMEM_FLOATS * (int)sizeof(float));
        smem_set = 1;
    }

    k0_split<<<(Nn * Nn) / 256, 256>>>(adj, ahi, alo);
    k1_gcn<<<RTOT / 32, 256>>>(x, W1, b1, g1, be1, W2, b2, sp);
    k2_mma<<<dim3(4, BS / 4), 256, K2_SMEM_FLOATS * sizeof(float)>>>(ahi, alo, sp, th);
    k3_mma<<<RTOT / 128, 256, K3_SMEM_FLOATS * sizeof(float)>>>(th, g2, be2, w_ih, b_ih, gv);
    k4_gru<<<BN / 8, 256>>>(gv, w_hh, b_hh, out);
}

// round 7
// speedup vs baseline: 2.7599x; 1.7281x over previous
#include <cuda_runtime.h>
#include <cuda_bf16.h>
#include <math.h>
#include <stdint.h>

#define Bb   8
#define Ss   256
#define Nn   512
#define Ii   32
#define HH   64
#define Oo   32
#define BS   (Bb*Ss)                 // 2048
#define RTOT (BS*Nn)                 // 1,048,576 rows
#define BN   (Bb*Nn)                 // 4096 GRU sequences

// Scratch
__device__ float g_sp  [(size_t)RTOT * Oo];
__device__ float g_tanh[(size_t)RTOT * Oo];
__device__ float g_gi  [(size_t)RTOT * 96];       // [(b*256+s)*512+n][96]
__device__ __nv_bfloat16 g_adjh[Nn * Nn];
__device__ __nv_bfloat16 g_adjl[Nn * Nn];

__device__ __forceinline__ float warp_sum(float v) {
    #pragma unroll
    for (int o = 16; o > 0; o >>= 1) v += __shfl_xor_sync(0xffffffffu, v, o);
    return v;
}
__device__ __forceinline__ float sigmoid_f(float x) {
    return __fdividef(1.f, 1.f + __expf(-x));
}
__device__ __forceinline__ float tanh_f(float x) {
    float ax = fabsf(x);
    float e  = __expf(-2.f * ax);
    float t  = (1.f - e) * __fdividef(1.f, 1.f + e);
    return copysignf(t, x);
}
__device__ __forceinline__ float tf32_rna(float v) {
    uint32_t u; asm("cvt.rna.tf32.f32 %0,%1;" : "=r"(u) : "f"(v));
    return __uint_as_float(u);
}
__device__ __forceinline__ uint32_t as_u(float f) { return __float_as_uint(f); }
__device__ __forceinline__ float bf_hi(float v) {
    return __bfloat162float(__float2bfloat16_rn(v));
}
__device__ __forceinline__ uint32_t bfpack(float a, float b) {
    __nv_bfloat162 t = __floats2bfloat162_rn(a, b);
    return *reinterpret_cast<uint32_t*>(&t);
}

struct F4 { float x, y, z, w; };
__device__ __forceinline__ void mma_tf32(F4& d,
    uint32_t a0, uint32_t a1, uint32_t a2, uint32_t a3, uint32_t b0, uint32_t b1)
{
    asm volatile(
        "mma.sync.aligned.m16n8k8.row.col.f32.tf32.tf32.f32 "
        "{%0,%1,%2,%3},{%4,%5,%6,%7},{%8,%9},{%0,%1,%2,%3};"
        : "+f"(d.x), "+f"(d.y), "+f"(d.z), "+f"(d.w)
        : "r"(a0), "r"(a1), "r"(a2), "r"(a3), "r"(b0), "r"(b1));
}
__device__ __forceinline__ void mma_bf16(F4& d,
    uint32_t a0, uint32_t a1, uint32_t a2, uint32_t a3, uint32_t b0, uint32_t b1)
{
    asm volatile(
        "mma.sync.aligned.m16n8k16.row.col.f32.bf16.bf16.f32 "
        "{%0,%1,%2,%3},{%4,%5,%6,%7},{%8,%9},{%0,%1,%2,%3};"
        : "+f"(d.x), "+f"(d.y), "+f"(d.z), "+f"(d.w)
        : "r"(a0), "r"(a1), "r"(a2), "r"(a3), "r"(b0), "r"(b1));
}
__device__ __forceinline__ void cp4(uint32_t dst, const float* src) {
    asm volatile("cp.async.ca.shared.global [%0], [%1], 4;" :: "r"(dst), "l"(src));
}

// ---------------------------------------------------------------------------
// K0: split adj into bf16 hi + bf16 residual
// ---------------------------------------------------------------------------
__global__ __launch_bounds__(256) void k0_split(
    const float* __restrict__ adj,
    __nv_bfloat16* __restrict__ hi, __nv_bfloat16* __restrict__ lo)
{
    int i = blockIdx.x * 256 + threadIdx.x;
    float v = adj[i];
    __nv_bfloat16 h = __float2bfloat16_rn(v);
    hi[i] = h;
    lo[i] = __float2bfloat16_rn(v - __bfloat162float(h));
}

// ---------------------------------------------------------------------------
// K1 (NEW, bf16 MMA): per 128-row block:
//   t = x@W1 + b1 (MMA1, 3-pass bf16) ; LN64+relu in-register on D frags ;
//   sp = h@W2 + b2 + x (MMA2 — D frags of MMA1 ARE A frags of MMA2).
// ---------------------------------------------------------------------------
__global__ __launch_bounds__(256) void k1_mma(
    const float* __restrict__ x,  const float* __restrict__ W1,
    const float* __restrict__ b1, const float* __restrict__ g1,
    const float* __restrict__ be1,const float* __restrict__ W2,
    const float* __restrict__ b2, float* __restrict__ sp_out)
{
    __shared__ uint32_t W1fh[1536], W1fl[1536];  // [(kt*2+half)*384 + lane*12 + j], j<8
    __shared__ uint32_t W2fh[3072], W2fl[3072];  // [(kt*2+half)*384 + lane*12 + j], j<4
    __shared__ float2 b1p[32], g1p[32], be1p[32], b2p[16];

    int tid = threadIdx.x, lane = tid & 31, wid = tid >> 5;
    int r = lane >> 2, c = lane & 3;
    size_t row0 = (size_t)blockIdx.x * 128;

    // stage W1 frags (32k x 64n): 1024 bf16x2 units
    #pragma unroll
    for (int p = 0; p < 4; p++) {
        int i = p * 256 + tid;
        int kp = i >> 6, n = i & 63;
        float wa = W1[(2 * kp) * 64 + n], wb = W1[(2 * kp + 1) * 64 + n];
        float ha = bf_hi(wa), hb = bf_hi(wb);
        int kt = kp >> 3, kpl = kp & 7, half = kpl >> 2, cc = kpl & 3;
        int j = n >> 3, rr = n & 7;
        int idx = (kt * 2 + half) * 384 + (rr * 4 + cc) * 12 + j;
        W1fh[idx] = bfpack(ha, hb);
        W1fl[idx] = bfpack(wa - ha, wb - hb);
    }
    // stage W2 frags (64k x 32n): 1024 units
    #pragma unroll
    for (int p = 0; p < 4; p++) {
        int i = p * 256 + tid;
        int kp = i >> 5, n = i & 31;
        float wa = W2[(2 * kp) * 32 + n], wb = W2[(2 * kp + 1) * 32 + n];
        float ha = bf_hi(wa), hb = bf_hi(wb);
        int kt = kp >> 3, kpl = kp & 7, half = kpl >> 2, cc = kpl & 3;
        int j = n >> 3, rr = n & 7;
        int idx = (kt * 2 + half) * 384 + (rr * 4 + cc) * 12 + j;
        W2fh[idx] = bfpack(ha, hb);
        W2fl[idx] = bfpack(wa - ha, wb - hb);
    }
    if (tid < 32) {
        b1p[tid]  = ((const float2*)b1)[tid];
        g1p[tid]  = ((const float2*)g1)[tid];
        be1p[tid] = ((const float2*)be1)[tid];
        if (tid < 16) b2p[tid] = ((const float2*)b2)[tid];
    }
    __syncthreads();

    // load x frags (fp32 kept for residual), split to bf16
    const float* xr  = x + (row0 + wid * 16 + r) * 32;
    const float* xr8 = xr + 8 * 32;
    float2 xa0[2], xa1[2], xa2[2], xa3[2];
    uint32_t A1h[2][4], A1l[2][4];
    #pragma unroll
    for (int kt = 0; kt < 2; kt++) {
        xa0[kt] = ((const float2*)xr)[kt * 8 + c];
        xa2[kt] = ((const float2*)xr)[kt * 8 + 4 + c];
        xa1[kt] = ((const float2*)xr8)[kt * 8 + c];
        xa3[kt] = ((const float2*)xr8)[kt * 8 + 4 + c];
        float h;
        h = bf_hi(xa0[kt].x); float h2 = bf_hi(xa0[kt].y);
        A1h[kt][0] = bfpack(h, h2); A1l[kt][0] = bfpack(xa0[kt].x - h, xa0[kt].y - h2);
        h = bf_hi(xa1[kt].x); h2 = bf_hi(xa1[kt].y);
        A1h[kt][1] = bfpack(h, h2); A1l[kt][1] = bfpack(xa1[kt].x - h, xa1[kt].y - h2);
        h = bf_hi(xa2[kt].x); h2 = bf_hi(xa2[kt].y);
        A1h[kt][2] = bfpack(h, h2); A1l[kt][2] = bfpack(xa2[kt].x - h, xa2[kt].y - h2);
        h = bf_hi(xa3[kt].x); h2 = bf_hi(xa3[kt].y);
        A1h[kt][3] = bfpack(h, h2); A1l[kt][3] = bfpack(xa3[kt].x - h, xa3[kt].y - h2);
    }

    // MMA1: t[128x64] = x @ W1
    F4 acc1[8];
    #pragma unroll
    for (int j = 0; j < 8; j++) { acc1[j].x = acc1[j].y = acc1[j].z = acc1[j].w = 0.f; }
    #pragma unroll
    for (int kt = 0; kt < 2; kt++) {
        uint32_t bh0[8], bh1[8], bl0[8], bl1[8];
        {
            const uint4* p0 = (const uint4*)&W1fh[(kt * 2 + 0) * 384 + lane * 12];
            const uint4* p1 = (const uint4*)&W1fh[(kt * 2 + 1) * 384 + lane * 12];
            const uint4* q0 = (const uint4*)&W1fl[(kt * 2 + 0) * 384 + lane * 12];
            const uint4* q1 = (const uint4*)&W1fl[(kt * 2 + 1) * 384 + lane * 12];
            uint4 t;
            t = p0[0]; bh0[0]=t.x; bh0[1]=t.y; bh0[2]=t.z; bh0[3]=t.w;
            t = p0[1]; bh0[4]=t.x; bh0[5]=t.y; bh0[6]=t.z; bh0[7]=t.w;
            t = p1[0]; bh1[0]=t.x; bh1[1]=t.y; bh1[2]=t.z; bh1[3]=t.w;
            t = p1[1]; bh1[4]=t.x; bh1[5]=t.y; bh1[6]=t.z; bh1[7]=t.w;
            t = q0[0]; bl0[0]=t.x; bl0[1]=t.y; bl0[2]=t.z; bl0[3]=t.w;
            t = q0[1]; bl0[4]=t.x; bl0[5]=t.y; bl0[6]=t.z; bl0[7]=t.w;
            t = q1[0]; bl1[0]=t.x; bl1[1]=t.y; bl1[2]=t.z; bl1[3]=t.w;
            t = q1[1]; bl1[4]=t.x; bl1[5]=t.y; bl1[6]=t.z; bl1[7]=t.w;
        }
        #pragma unroll
        for (int j = 0; j < 8; j++) {
            mma_bf16(acc1[j], A1h[kt][0], A1h[kt][1], A1h[kt][2], A1h[kt][3], bh0[j], bh1[j]);
            mma_bf16(acc1[j], A1l[kt][0], A1l[kt][1], A1l[kt][2], A1l[kt][3], bh0[j], bh1[j]);
            mma_bf16(acc1[j], A1h[kt][0], A1h[kt][1], A1h[kt][2], A1h[kt][3], bl0[j], bl1[j]);
        }
    }

    // + b1, LN64 (rows r and r+8), relu — all in-register
    float s0 = 0.f, q0s = 0.f, s1 = 0.f, q1s = 0.f;
    #pragma unroll
    for (int j = 0; j < 8; j++) {
        float2 b = b1p[c + 4 * j];
        acc1[j].x += b.x; acc1[j].y += b.y; acc1[j].z += b.x; acc1[j].w += b.y;
        s0 += acc1[j].x + acc1[j].y;
        q0s += acc1[j].x * acc1[j].x + acc1[j].y * acc1[j].y;
        s1 += acc1[j].z + acc1[j].w;
        q1s += acc1[j].z * acc1[j].z + acc1[j].w * acc1[j].w;
    }
    s0 += __shfl_xor_sync(0xffffffffu, s0, 1); s0 += __shfl_xor_sync(0xffffffffu, s0, 2);
    q0s += __shfl_xor_sync(0xffffffffu, q0s, 1); q0s += __shfl_xor_sync(0xffffffffu, q0s, 2);
    s1 += __shfl_xor_sync(0xffffffffu, s1, 1); s1 += __shfl_xor_sync(0xffffffffu, s1, 2);
    q1s += __shfl_xor_sync(0xffffffffu, q1s, 1); q1s += __shfl_xor_sync(0xffffffffu, q1s, 2);
    float mu0 = s0 * (1.f / 64.f), mu1 = s1 * (1.f / 64.f);
    float rstd0 = rsqrtf(fmaf(-mu0, mu0, q0s * (1.f / 64.f)) + 1e-5f);
    float rstd1 = rsqrtf(fmaf(-mu1, mu1, q1s * (1.f / 64.f)) + 1e-5f);
    #pragma unroll
    for (int j = 0; j < 8; j++) {
        float2 g = g1p[c + 4 * j], be = be1p[c + 4 * j];
        acc1[j].x = fmaxf(fmaf((acc1[j].x - mu0) * rstd0, g.x, be.x), 0.f);
        acc1[j].y = fmaxf(fmaf((acc1[j].y - mu0) * rstd0, g.y, be.y), 0.f);
        acc1[j].z = fmaxf(fmaf((acc1[j].z - mu1) * rstd1, g.x, be.x), 0.f);
        acc1[j].w = fmaxf(fmaf((acc1[j].w - mu1) * rstd1, g.y, be.y), 0.f);
    }

    // h D-frags -> A-frags for GEMM2 (k=64, kt 0..3), bf16 split
    uint32_t A2h[4][4], A2l[4][4];
    #pragma unroll
    for (int kt = 0; kt < 4; kt++) {
        F4 e = acc1[2 * kt], o = acc1[2 * kt + 1];
        float h;
        h = bf_hi(e.x); float h2 = bf_hi(e.y);
        A2h[kt][0] = bfpack(h, h2); A2l[kt][0] = bfpack(e.x - h, e.y - h2);
        h = bf_hi(e.z); h2 = bf_hi(e.w);
        A2h[kt][1] = bfpack(h, h2); A2l[kt][1] = bfpack(e.z - h, e.w - h2);
        h = bf_hi(o.x); h2 = bf_hi(o.y);
        A2h[kt][2] = bfpack(h, h2); A2l[kt][2] = bfpack(o.x - h, o.y - h2);
        h = bf_hi(o.z); h2 = bf_hi(o.w);
        A2h[kt][3] = bfpack(h, h2); A2l[kt][3] = bfpack(o.z - h, o.w - h2);
    }

    // MMA2: sp = h @ W2
    F4 acc2[4];
    #pragma unroll
    for (int j = 0; j < 4; j++) { acc2[j].x = acc2[j].y = acc2[j].z = acc2[j].w = 0.f; }
    #pragma unroll
    for (int kt = 0; kt < 4; kt++) {
        uint4 h0 = *(const uint4*)&W2fh[(kt * 2 + 0) * 384 + lane * 12];
        uint4 h1 = *(const uint4*)&W2fh[(kt * 2 + 1) * 384 + lane * 12];
        uint4 l0 = *(const uint4*)&W2fl[(kt * 2 + 0) * 384 + lane * 12];
        uint4 l1 = *(const uint4*)&W2fl[(kt * 2 + 1) * 384 + lane * 12];
        uint32_t bh0[4] = {h0.x, h0.y, h0.z, h0.w};
        uint32_t bh1[4] = {h1.x, h1.y, h1.z, h1.w};
        uint32_t bl0[4] = {l0.x, l0.y, l0.z, l0.w};
        uint32_t bl1[4] = {l1.x, l1.y, l1.z, l1.w};
        #pragma unroll
        for (int j = 0; j < 4; j++) {
            mma_bf16(acc2[j], A2h[kt][0], A2h[kt][1], A2h[kt][2], A2h[kt][3], bh0[j], bh1[j]);
            mma_bf16(acc2[j], A2l[kt][0], A2l[kt][1], A2l[kt][2], A2l[kt][3], bh0[j], bh1[j]);
            mma_bf16(acc2[j], A2h[kt][0], A2h[kt][1], A2h[kt][2], A2h[kt][3], bl0[j], bl1[j]);
        }
    }

    // epilogue: + b2 + x residual, store
    size_t orow = row0 + wid * 16 + r;
    #pragma unroll
    for (int j = 0; j < 4; j++) {
        float2 b = b2p[4 * j + c];
        int kth = j >> 1;
        float2 rx0 = (j & 1) ? xa2[kth] : xa0[kth];
        float2 rx1 = (j & 1) ? xa3[kth] : xa1[kth];
        float2 v0 = { acc2[j].x + b.x + rx0.x, acc2[j].y + b.y + rx0.y };
        float2 v1 = { acc2[j].z + b.x + rx1.x, acc2[j].w + b.y + rx1.y };
        *(float2*)&sp_out[orow * 32 + 8 * j + 2 * c]       = v0;
        *(float2*)&sp_out[(orow + 8) * 32 + 8 * j + 2 * c] = v1;
    }
}

// ---------------------------------------------------------------------------
// K2 (bf16 m16n8k16, 3-pass): out[bs,n,f] = tanh(sum_m adj[n,m]*sp[bs,m,f])
// Tile 128n x 32f x 4bs, K-chunk 32 (2 k16 steps). Fragment-major smem.
// ---------------------------------------------------------------------------
__global__ __launch_bounds__(256) void k2_mma(
    const __nv_bfloat16* __restrict__ adjh, const __nv_bfloat16* __restrict__ adjl,
    const float* __restrict__ sp, float* __restrict__ out)
{
    __shared__ uint32_t Ahs[2048], Als[2048];   // [(w*2+kt)*128 + lane*4 + reg]
    __shared__ uint32_t Bhs[2560], Bls[2560];   // [((u*2+kt)*2+half)*160 + c*40 + r*4 + j]

    int tid = threadIdx.x, lane = tid & 31, wid = tid >> 5;
    int n0  = blockIdx.x * 128;
    int bs0 = blockIdx.y * 4;
    int r = lane >> 2, c = lane & 3;

    F4 acc[4][4];
    #pragma unroll
    for (int u = 0; u < 4; u++)
        #pragma unroll
        for (int j = 0; j < 4; j++) { acc[u][j].x = acc[u][j].y = acc[u][j].z = acc[u][j].w = 0.f; }

    for (int mc = 0; mc < 512; mc += 32) {
        __syncthreads();
        // stage A (adj, pre-split bf16)
        #pragma unroll
        for (int p = 0; p < 2; p++) {
            int i = p * 256 + tid;
            int n = i >> 2, seg = i & 3;
            size_t boff = ((size_t)(n0 + n) * 512 + mc) * 2 + seg * 16;
            uint4 vh = *(const uint4*)((const char*)adjh + boff);
            uint4 vl = *(const uint4*)((const char*)adjl + boff);
            int w = n >> 4, rr = n & 15, rf = rr & 7, rh = rr >> 3, kt = seg >> 1;
            int base = (w * 2 + kt) * 128 + rf * 16;
            uint32_t ah[4] = {vh.x, vh.y, vh.z, vh.w};
            uint32_t al[4] = {vl.x, vl.y, vl.z, vl.w};
            #pragma unroll
            for (int u = 0; u < 4; u++) {
                int kpl = (seg & 1) * 4 + u;
                int cc = kpl & 3, side = kpl >> 2;
                Ahs[base + cc * 4 + side * 2 + rh] = ah[u];
                Als[base + cc * 4 + side * 2 + rh] = al[u];
            }
        }
        // stage B (sp, split to bf16 pairs along k)
        #pragma unroll
        for (int p = 0; p < 2; p++) {
            int u = p * 2 + (tid >> 7);
            int rem = tid & 127;
            int kp = rem >> 3, q = rem & 7, col0 = q * 4;
            const float* s0 = &sp[((size_t)(bs0 + u) * 512 + mc + 2 * kp) * 32 + col0];
            float4 va = *(const float4*)s0;
            float4 vb = *(const float4*)(s0 + 32);
            int kt = kp >> 3, kpl = kp & 7, half = kpl >> 2, cc = kpl & 3;
            int bb = ((u * 2 + kt) * 2 + half) * 160 + cc * 40;
            float aa[4] = {va.x, va.y, va.z, va.w};
            float bbv[4] = {vb.x, vb.y, vb.z, vb.w};
            #pragma unroll
            for (int i = 0; i < 4; i++) {
                int col = col0 + i, j = col >> 3, rr = col & 7;
                float ha = bf_hi(aa[i]), hb = bf_hi(bbv[i]);
                Bhs[bb + rr * 4 + j] = bfpack(ha, hb);
                Bls[bb + rr * 4 + j] = bfpack(aa[i] - ha, bbv[i] - hb);
            }
        }
        __syncthreads();

        #pragma unroll
        for (int kt = 0; kt < 2; kt++) {
            uint4 Ah4 = *(const uint4*)&Ahs[(wid * 2 + kt) * 128 + lane * 4];
            uint4 Al4 = *(const uint4*)&Als[(wid * 2 + kt) * 128 + lane * 4];
            #pragma unroll
            for (int u = 0; u < 4; u++) {
                int bb = ((u * 2 + kt) * 2) * 160 + c * 40 + r * 4;
                uint4 h0 = *(const uint4*)&Bhs[bb];
                uint4 h1 = *(const uint4*)&Bhs[bb + 160];
                uint4 l0 = *(const uint4*)&Bls[bb];
                uint4 l1 = *(const uint4*)&Bls[bb + 160];
                uint32_t bh0[4] = {h0.x, h0.y, h0.z, h0.w};
                uint32_t bh1[4] = {h1.x, h1.y, h1.z, h1.w};
                uint32_t bl0[4] = {l0.x, l0.y, l0.z, l0.w};
                uint32_t bl1[4] = {l1.x, l1.y, l1.z, l1.w};
                #pragma unroll
                for (int j = 0; j < 4; j++) {
                    mma_bf16(acc[u][j], Ah4.x, Ah4.y, Ah4.z, Ah4.w, bh0[j], bh1[j]);
                    mma_bf16(acc[u][j], Al4.x, Al4.y, Al4.z, Al4.w, bh0[j], bh1[j]);
                    mma_bf16(acc[u][j], Ah4.x, Ah4.y, Ah4.z, Ah4.w, bl0[j], bl1[j]);
                }
            }
        }
    }

    int c2 = c * 2;
    #pragma unroll
    for (int u = 0; u < 4; u++) {
        size_t bsrow = (size_t)(bs0 + u) * 512;
        #pragma unroll
        for (int j = 0; j < 4; j++) {
            int col  = j * 8 + c2;
            int row0 = n0 + wid * 16 + r;
            float2 v0 = { tanh_f(acc[u][j].x), tanh_f(acc[u][j].y) };
            float2 v1 = { tanh_f(acc[u][j].z), tanh_f(acc[u][j].w) };
            *(float2*)&out[(bsrow + row0)     * 32 + col] = v0;
            *(float2*)&out[(bsrow + row0 + 8) * 32 + col] = v1;
        }
    }
}

// ---------------------------------------------------------------------------
// K3: LN32 per row + tf32 MMA: gi = ln @ w_ih^T + b_ih. (unchanged)
// ---------------------------------------------------------------------------
#define K3_SMEM_FLOATS (2*128*36 + 2*32*104 + 96)

__global__ __launch_bounds__(256) void k3_mma(
    const float* __restrict__ tin, const float* __restrict__ g2,
    const float* __restrict__ be2, const float* __restrict__ w_ih,
    const float* __restrict__ b_ih, float* __restrict__ gi)
{
    extern __shared__ float smem[];
    float* Ah  = smem;
    float* Al  = Ah + 128 * 36;
    float* Bh  = Al + 128 * 36;
    float* Bl  = Bh + 32 * 104;
    float* bis = Bl + 32 * 104;

    int tid = threadIdx.x, lane = tid & 31, wid = tid >> 5;
    size_t rr0 = (size_t)blockIdx.x * 128;

    #pragma unroll
    for (int p = 0; p < 12; p++) {
        int idx = p * 256 + tid;
        int o = idx >> 5, j = idx & 31;
        float v = w_ih[idx];
        float h = tf32_rna(v);
        Bh[j * 104 + o] = h;
        Bl[j * 104 + o] = v - h;
    }
    if (tid < 96) bis[tid] = b_ih[tid];

    float g2v = g2[lane], be2v = be2[lane];
    #pragma unroll
    for (int q = 0; q < 16; q++) {
        int row = wid * 16 + q;
        float v = tin[(rr0 + row) * 32 + lane];
        float mu = warp_sum(v) * (1.f / 32.f);
        float d = v - mu;
        float var = warp_sum(d * d) * (1.f / 32.f);
        float ln = fmaf(d * rsqrtf(var + 1e-5f), g2v, be2v);
        float lh = tf32_rna(ln);
        Ah[row * 36 + lane] = lh;
        Al[row * 36 + lane] = ln - lh;
    }
    __syncthreads();

    int r = lane >> 2, c = lane & 3;
    int mbase = wid * 16;
    F4 acc[12];
    #pragma unroll
    for (int j = 0; j < 12; j++) { acc[j].x = acc[j].y = acc[j].z = acc[j].w = 0.f; }

    #pragma unroll
    for (int kt = 0; kt < 4; kt++) {
        int kb = kt * 8;
        uint32_t ah0 = as_u(Ah[(mbase + r)     * 36 + kb + c]);
        uint32_t ah1 = as_u(Ah[(mbase + 8 + r) * 36 + kb + c]);
        uint32_t ah2 = as_u(Ah[(mbase + r)     * 36 + kb + 4 + c]);
        uint32_t ah3 = as_u(Ah[(mbase + 8 + r) * 36 + kb + 4 + c]);
        uint32_t al0 = as_u(Al[(mbase + r)     * 36 + kb + c]);
        uint32_t al1 = as_u(Al[(mbase + 8 + r) * 36 + kb + c]);
        uint32_t al2 = as_u(Al[(mbase + r)     * 36 + kb + 4 + c]);
        uint32_t al3 = as_u(Al[(mbase + 8 + r) * 36 + kb + 4 + c]);
        #pragma unroll
        for (int j = 0; j < 12; j++) {
            uint32_t bh0 = as_u(Bh[(kb + c)     * 104 + j * 8 + r]);
            uint32_t bh1 = as_u(Bh[(kb + 4 + c) * 104 + j * 8 + r]);
            uint32_t bl0 = as_u(Bl[(kb + c)     * 104 + j * 8 + r]);
            uint32_t bl1 = as_u(Bl[(kb + 4 + c) * 104 + j * 8 + r]);
            mma_tf32(acc[j], ah0, ah1, ah2, ah3, bh0, bh1);
            mma_tf32(acc[j], al0, al1, al2, al3, bh0, bh1);
            mma_tf32(acc[j], ah0, ah1, ah2, ah3, bl0, bl1);
        }
    }

    int c2 = (lane & 3) * 2;
    #pragma unroll
    for (int j = 0; j < 12; j++) {
        int col = j * 8 + c2;
        float2 bi = *(const float2*)&bis[col];
        size_t row0 = rr0 + mbase + r;
        float2 v0 = { acc[j].x + bi.x, acc[j].y + bi.y };
        float2 v1 = { acc[j].z + bi.x, acc[j].w + bi.y };
        *(float2*)&gi[row0 * 96 + col]       = v0;
        *(float2*)&gi[(row0 + 8) * 96 + col] = v1;
    }
}

// ---------------------------------------------------------------------------
// K4: GRU scan (unchanged): cp.async 8-stage ring, 16+16 split chains.
// ---------------------------------------------------------------------------
__global__ __launch_bounds__(256) void k4_gru(
    const float* __restrict__ gi, const float* __restrict__ w_hh,
    const float* __restrict__ b_hh, float* __restrict__ out)
{
    __shared__ float gbuf[8][8][96];

    int tid = threadIdx.x, lane = tid & 31, wr = tid >> 5;
    int bn = blockIdx.x * 8 + wr;
    int b = bn >> 9, n = bn & 511;

    float w0[32], w1[32], w2[32];
    #pragma unroll
    for (int m = 0; m < 8; m++) {
        float4 a = ((const float4*)(w_hh + (size_t)lane * 32))[m];
        float4 c = ((const float4*)(w_hh + (size_t)(lane + 32) * 32))[m];
        float4 d = ((const float4*)(w_hh + (size_t)(lane + 64) * 32))[m];
        w0[4*m+0]=a.x; w0[4*m+1]=a.y; w0[4*m+2]=a.z; w0[4*m+3]=a.w;
        w1[4*m+0]=c.x; w1[4*m+1]=c.y; w1[4*m+2]=c.z; w1[4*m+3]=c.w;
        w2[4*m+0]=d.x; w2[4*m+1]=d.y; w2[4*m+2]=d.z; w2[4*m+3]=d.w;
    }
    float bh0 = b_hh[lane], bh1 = b_hh[lane + 32], bh2 = b_hh[lane + 64];

    const size_t tstride = (size_t)512 * 96;
    const float* gbase = gi + ((size_t)(b * 256) * 512 + n) * 96;

    #pragma unroll
    for (int s = 0; s < 7; s++) {
        const float* src = gbase + (size_t)s * tstride;
        uint32_t d = (uint32_t)__cvta_generic_to_shared(&gbuf[wr][s][lane]);
        cp4(d, src + lane);
        cp4(d + 128, src + lane + 32);
        cp4(d + 256, src + lane + 64);
        asm volatile("cp.async.commit_group;" ::: "memory");
    }

    float h = 0.f;
    for (int t = 0; t < 256; t++) {
        if (t + 7 < 256) {
            const float* src = gbase + (size_t)(t + 7) * tstride;
            uint32_t d = (uint32_t)__cvta_generic_to_shared(&gbuf[wr][(t + 7) & 7][lane]);
            cp4(d, src + lane);
            cp4(d + 128, src + lane + 32);
            cp4(d + 256, src + lane + 64);
        }
        asm volatile("cp.async.commit_group;" ::: "memory");
        asm volatile("cp.async.wait_group 7;" ::: "memory");

        int s = t & 7;
        float q0 = gbuf[wr][s][lane];
        float q1 = gbuf[wr][s][lane + 32];
        float q2 = gbuf[wr][s][lane + 64];

        float a0 = bh0, a1 = bh1, a2 = bh2;
        float e0 = 0.f, e1 = 0.f, e2 = 0.f;
        #pragma unroll
        for (int jj = 0; jj < 16; jj++) {
            float hv = __shfl_sync(0xffffffffu, h, jj);
            float hw = __shfl_sync(0xffffffffu, h, jj + 16);
            a0 = fmaf(hv, w0[jj], a0);
            e0 = fmaf(hw, w0[jj + 16], e0);
            a1 = fmaf(hv, w1[jj], a1);
            e1 = fmaf(hw, w1[jj + 16], e1);
            a2 = fmaf(hv, w2[jj], a2);
            e2 = fmaf(hw, w2[jj + 16], e2);
        }
        a0 += e0; a1 += e1; a2 += e2;

        float rg = sigmoid_f(q0 + a0);
        float zg = sigmoid_f(q1 + a1);
        float ng = tanh_f(fmaf(rg, a2, q2));
        h = fmaf(zg, h - ng, ng);
        out[((size_t)(b * 256 + t) * 512 + n) * 32 + lane] = h;
    }
}

// ---------------------------------------------------------------------------
extern "C" void kernel_launch(void* const* d_in, const int* in_sizes, int n_in,
                              void* d_out, int out_size)
{
    (void)in_sizes; (void)n_in; (void)out_size;
    const float* x    = (const float*)d_in[0];
    const float* adj  = (const float*)d_in[1];
    const float* W1   = (const float*)d_in[2];
    const float* b1   = (const float*)d_in[3];
    const float* g1   = (const float*)d_in[4];
    const float* be1  = (const float*)d_in[5];
    const float* W2   = (const float*)d_in[6];
    const float* b2   = (const float*)d_in[7];
    const float* g2   = (const float*)d_in[8];
    const float* be2  = (const float*)d_in[9];
    const float* w_ih = (const float*)d_in[10];
    const float* w_hh = (const float*)d_in[11];
    const float* b_ih = (const float*)d_in[12];
    const float* b_hh = (const float*)d_in[13];
    float* out = (float*)d_out;

    float *sp, *th, *gv;
    __nv_bfloat16 *ah, *al;
    cudaGetSymbolAddress((void**)&sp, g_sp);
    cudaGetSymbolAddress((void**)&th, g_tanh);
    cudaGetSymbolAddress((void**)&gv, g_gi);
    cudaGetSymbolAddress((void**)&ah, g_adjh);
    cudaGetSymbolAddress((void**)&al, g_adjl);

    static int smem_set = 0;
    if (!smem_set) {
        cudaFuncSetAttribute(k3_mma, cudaFuncAttributeMaxDynamicSharedMemorySize,
                             K3_SMEM_FLOATS * (int)sizeof(float));
        smem_set = 1;
    }

    k0_split<<<(Nn * Nn) / 256, 256>>>(adj, ah, al);
    k1_mma<<<RTOT / 128, 256>>>(x, W1, b1, g1, be1, W2, b2, sp);
    k2_mma<<<dim3(4, BS / 4), 256>>>(ah, al, sp, th);
    k3_mma<<<RTOT / 128, 256, K3_SMEM_FLOATS * sizeof(float)>>>(th, g2, be2, w_ih, b_ih, gv);
    k4_gru<<<BN / 8, 256>>>(gv, w_hh, b_hh, out);
}